// round 3
// baseline (speedup 1.0000x reference)
#include <cuda_runtime.h>
#include <cuda_bf16.h>

#define NN     50000
#define IN_C   256
#define HID_C  128
#define OUT_C  64

// ---------------- scratch ----------------
__device__ __align__(16) float g_deg [NN];
__device__ __align__(16) float g_dinv[NN];
__device__ __align__(16) float g_h2  [NN * HID_C];   // dinv * (x @ W1)  (read source)
__device__ __align__(16) float g_acc1[NN * HID_C];   // accumulator layer 1
__device__ __align__(16) float g_z2  [NN * OUT_C];   // dinv * (relu(...) @ W2)

// ---------------- degree / norm ----------------
__global__ void zero_deg_kernel(float* deg, int n) {
    int i = blockIdx.x * blockDim.x + threadIdx.x;
    if (i < n) deg[i] = 0.0f;
}
__global__ void count_deg_kernel(const int* __restrict__ dst, float* __restrict__ deg, int E) {
    int e = blockIdx.x * blockDim.x + threadIdx.x;
    if (e < E) atomicAdd(&deg[dst[e]], 1.0f);
}
__global__ void dinv_kernel(const float* __restrict__ deg, float* __restrict__ dinv, int n) {
    int i = blockIdx.x * blockDim.x + threadIdx.x;
    if (i < n) dinv[i] = rsqrtf(deg[i] + 1.0f);   // +1 self loop
}

// ---------------- SGEMM with fused transforms --------------------------------
// C = op(A) @ B ; op(A)=A (TRANS_A=false) or relu(tbias + dinv[r]*A) (true).
// Epilogue: v = dinv[r] * acc, stored to BOTH C1 and C2.
// BK=16, 256 threads, (BM/TM)*(BN/TN)==256.
template<int BM, int BN, int TM, int TN, bool TRANS_A>
__global__ void sgemm_fused(const float* __restrict__ A, const float* __restrict__ B,
                            float* __restrict__ C1, float* __restrict__ C2,
                            const float* __restrict__ dinv, const float* __restrict__ tbias,
                            int M, int K, int Nc) {
    const int BK = 16;
    __shared__ __align__(16) float As[BK][BM];
    __shared__ __align__(16) float Bs[BK][BN];

    const int tid  = threadIdx.x;
    const int row0 = blockIdx.x * BM;
    const int col0 = blockIdx.y * BN;

    // A-load indices: each thread loads float4 along K
    const int a_row = tid >> 2;            // 0..63
    const int a_k   = (tid & 3) * 4;       // 0,4,8,12
    // B-load indices
    const int BN4      = BN / 4;
    const int b_col    = (tid % BN4) * 4;
    const int b_row0   = tid / BN4;
    const int ROWS_PER = 256 / BN4;

    // fragment indices
    const int tx = tid % (BN / TN);
    const int ty = tid / (BN / TN);
    const int m0 = ty * TM;
    const int n0 = tx * TN;

    float acc[TM][TN];
    #pragma unroll
    for (int i = 0; i < TM; i++)
        #pragma unroll
        for (int j = 0; j < TN; j++) acc[i][j] = 0.0f;

    for (int k0 = 0; k0 < K; k0 += BK) {
        // ---- A tile ----
        #pragma unroll
        for (int s = 0; s < BM / 64; s++) {
            int arl = a_row + s * 64;
            int ar  = row0 + arl;
            float4 av = make_float4(0.f, 0.f, 0.f, 0.f);
            if (ar < M) {
                av = *reinterpret_cast<const float4*>(A + (long long)ar * K + k0 + a_k);
                if (TRANS_A) {
                    float di = dinv[ar];
                    float4 bb = *reinterpret_cast<const float4*>(tbias + k0 + a_k);
                    av.x = fmaxf(fmaf(di, av.x, bb.x), 0.f);
                    av.y = fmaxf(fmaf(di, av.y, bb.y), 0.f);
                    av.z = fmaxf(fmaf(di, av.z, bb.z), 0.f);
                    av.w = fmaxf(fmaf(di, av.w, bb.w), 0.f);
                }
            }
            As[a_k + 0][arl] = av.x;
            As[a_k + 1][arl] = av.y;
            As[a_k + 2][arl] = av.z;
            As[a_k + 3][arl] = av.w;
        }
        // ---- B tile ----
        #pragma unroll
        for (int s = 0; s < BK / ROWS_PER; s++) {
            int br = b_row0 + s * ROWS_PER;
            float4 bv = *reinterpret_cast<const float4*>(B + (long long)(k0 + br) * Nc + col0 + b_col);
            *reinterpret_cast<float4*>(&Bs[br][b_col]) = bv;
        }
        __syncthreads();

        #pragma unroll
        for (int k = 0; k < BK; k++) {
            float a[TM], b[TN];
            #pragma unroll
            for (int i = 0; i < TM / 4; i++) {
                float4 a4 = *reinterpret_cast<const float4*>(&As[k][m0 + i * 4]);
                a[i*4+0]=a4.x; a[i*4+1]=a4.y; a[i*4+2]=a4.z; a[i*4+3]=a4.w;
            }
            #pragma unroll
            for (int j = 0; j < TN / 4; j++) {
                float4 b4 = *reinterpret_cast<const float4*>(&Bs[k][n0 + j * 4]);
                b[j*4+0]=b4.x; b[j*4+1]=b4.y; b[j*4+2]=b4.z; b[j*4+3]=b4.w;
            }
            #pragma unroll
            for (int i = 0; i < TM; i++)
                #pragma unroll
                for (int j = 0; j < TN; j++)
                    acc[i][j] = fmaf(a[i], b[j], acc[i][j]);
        }
        __syncthreads();
    }

    // ---- epilogue: v = dinv[r]*acc -> C1 and C2 ----
    #pragma unroll
    for (int i = 0; i < TM; i++) {
        int r = row0 + m0 + i;
        if (r < M) {
            float s = dinv[r];
            #pragma unroll
            for (int j = 0; j < TN / 4; j++) {
                float4 v = make_float4(s * acc[i][j*4+0], s * acc[i][j*4+1],
                                       s * acc[i][j*4+2], s * acc[i][j*4+3]);
                long long off = (long long)r * Nc + col0 + n0 + j * 4;
                *reinterpret_cast<float4*>(C1 + off) = v;
                *reinterpret_cast<float4*>(C2 + off) = v;
            }
        }
    }
}

// ---------------- edge scatter: acc[dst] += h2[src] (pure) ------------------
template<int LOGC4, int C>
__global__ void scatter_kernel(const float* __restrict__ h2,
                               const int* __restrict__ src, const int* __restrict__ dst,
                               float* __restrict__ acc, int E) {
    const int C4 = 1 << LOGC4;
    long long idx = (long long)blockIdx.x * blockDim.x + threadIdx.x;
    long long total = (long long)E << LOGC4;
    if (idx >= total) return;
    int e = (int)(idx >> LOGC4);
    int c = (int)(idx & (C4 - 1)) * 4;
    int s = src[e];
    int d = dst[e];
    float4 v = *reinterpret_cast<const float4*>(h2 + (long long)s * C + c);
    atomicAdd(reinterpret_cast<float4*>(acc + (long long)d * C + c), v);
}

// ---------------- final fixup: out = b2 + dinv[i]*out -----------------------
__global__ void fixup_kernel(float* __restrict__ out, const float* __restrict__ dinv,
                             const float* __restrict__ b2, int n) {
    const int C4 = OUT_C / 4;
    int idx = blockIdx.x * blockDim.x + threadIdx.x;
    if (idx >= n * C4) return;
    int i = idx / C4;
    int c = (idx % C4) * 4;
    float di = dinv[i];
    float4 v = *reinterpret_cast<float4*>(out + (long long)i * OUT_C + c);
    float4 bb = *reinterpret_cast<const float4*>(b2 + c);
    v.x = fmaf(di, v.x, bb.x); v.y = fmaf(di, v.y, bb.y);
    v.z = fmaf(di, v.z, bb.z); v.w = fmaf(di, v.w, bb.w);
    *reinterpret_cast<float4*>(out + (long long)i * OUT_C + c) = v;
}

// ---------------- launch ----------------
extern "C" void kernel_launch(void* const* d_in, const int* in_sizes, int n_in,
                              void* d_out, int out_size) {
    const float* x  = (const float*)d_in[0];
    const int*   ei = (const int*)  d_in[1];
    const float* W1 = (const float*)d_in[2];
    const float* b1 = (const float*)d_in[3];
    const float* W2 = (const float*)d_in[4];
    const float* b2 = (const float*)d_in[5];
    float* out = (float*)d_out;

    const int E = in_sizes[1] / 2;
    const int* src = ei;
    const int* dst = ei + E;

    float *deg, *dinv, *h2, *acc1, *z2;
    cudaGetSymbolAddress((void**)&deg,  g_deg);
    cudaGetSymbolAddress((void**)&dinv, g_dinv);
    cudaGetSymbolAddress((void**)&h2,   g_h2);
    cudaGetSymbolAddress((void**)&acc1, g_acc1);
    cudaGetSymbolAddress((void**)&z2,   g_z2);

    // 1) normalization
    zero_deg_kernel<<<(NN + 255) / 256, 256>>>(deg, NN);
    count_deg_kernel<<<(E + 255) / 256, 256>>>(dst, deg, E);
    dinv_kernel<<<(NN + 255) / 256, 256>>>(deg, dinv, NN);

    // 2) GEMM1: h2 = dinv * (x @ W1); acc1 initialized to h2 (self-loop term)
    {
        dim3 grid((NN + 127) / 128, HID_C / 128);
        sgemm_fused<128, 128, 8, 8, false><<<grid, 256>>>(
            x, W1, h2, acc1, dinv, nullptr, NN, IN_C, HID_C);
    }
    // 3) scatter layer 1: acc1[dst] += h2[src]
    {
        long long etotal = (long long)E * (HID_C / 4);
        scatter_kernel<5, HID_C><<<(int)((etotal + 255) / 256), 256>>>(h2, src, dst, acc1, E);
    }
    // 4) GEMM2: A = relu(b1 + dinv*acc1); z2 = dinv*(A @ W2); out init = z2
    {
        dim3 grid((NN + 127) / 128, OUT_C / 64);
        sgemm_fused<128, 64, 8, 4, true><<<grid, 256>>>(
            acc1, W2, z2, out, dinv, b1, NN, HID_C, OUT_C);
    }
    // 5) scatter layer 2: out[dst] += z2[src]
    {
        long long etotal = (long long)E * (OUT_C / 4);
        scatter_kernel<4, OUT_C><<<(int)((etotal + 255) / 256), 256>>>(z2, src, dst, out, E);
    }
    // 6) out = b2 + dinv*out
    {
        int total = NN * (OUT_C / 4);
        fixup_kernel<<<(total + 255) / 256, 256>>>(out, dinv, b2, NN);
    }
}

// round 4
// speedup vs baseline: 1.1324x; 1.1324x over previous
#include <cuda_runtime.h>
#include <cuda_bf16.h>

#define NN     50000
#define IN_C   256
#define HID_C  128
#define OUT_C  64

// ---------------- scratch ----------------
__device__ __align__(16) float g_deg [NN];
__device__ __align__(16) float g_dinv[NN];
__device__ __align__(16) float g_h2  [NN * HID_C];   // dinv * (x @ W1)  (read source)
__device__ __align__(16) float g_acc1[NN * HID_C];   // accumulator layer 1
__device__ __align__(16) float g_z2  [NN * OUT_C];   // dinv * (relu(...) @ W2)

// ---------------- degree / norm ----------------
__global__ void zero_deg_kernel(float* deg, int n) {
    int i = blockIdx.x * blockDim.x + threadIdx.x;
    if (i < n) deg[i] = 0.0f;
}
__global__ void count_deg_kernel(const int* __restrict__ dst, float* __restrict__ deg, int E) {
    int e = blockIdx.x * blockDim.x + threadIdx.x;
    if (e < E) atomicAdd(&deg[dst[e]], 1.0f);
}
__global__ void dinv_kernel(const float* __restrict__ deg, float* __restrict__ dinv, int n) {
    int i = blockIdx.x * blockDim.x + threadIdx.x;
    if (i < n) dinv[i] = rsqrtf(deg[i] + 1.0f);   // +1 self loop
}

// ---------------- SGEMM with fused transforms --------------------------------
// C = op(A) @ B ; op(A)=A (TRANS_A=false) or relu(tbias + dinv[r]*A) (true).
// Epilogue: v = dinv[r] * acc, stored to BOTH C1 and C2.
// BM=128, BN=64, BK=16, TM=8, TN=4, 256 threads -> ~64 regs, 4 CTA/SM.
template<int BM, int BN, int TM, int TN, bool TRANS_A>
__global__ void sgemm_fused(const float* __restrict__ A, const float* __restrict__ B,
                            float* __restrict__ C1, float* __restrict__ C2,
                            const float* __restrict__ dinv, const float* __restrict__ tbias,
                            int M, int K, int Nc) {
    const int BK = 16;
    __shared__ __align__(16) float As[BK][BM];
    __shared__ __align__(16) float Bs[BK][BN];

    const int tid  = threadIdx.x;
    const int row0 = blockIdx.x * BM;
    const int col0 = blockIdx.y * BN;

    // A-load: each thread loads BM/64 float4s along K
    const int a_row = tid >> 2;            // 0..63
    const int a_k   = (tid & 3) * 4;       // 0,4,8,12
    // B-load
    const int BN4      = BN / 4;
    const int b_col    = (tid % BN4) * 4;
    const int b_row0   = tid / BN4;
    const int ROWS_PER = 256 / BN4;

    const int tx = tid % (BN / TN);
    const int ty = tid / (BN / TN);
    const int m0 = ty * TM;
    const int n0 = tx * TN;

    float acc[TM][TN];
    #pragma unroll
    for (int i = 0; i < TM; i++)
        #pragma unroll
        for (int j = 0; j < TN; j++) acc[i][j] = 0.0f;

    for (int k0 = 0; k0 < K; k0 += BK) {
        #pragma unroll
        for (int s = 0; s < BM / 64; s++) {
            int arl = a_row + s * 64;
            int ar  = row0 + arl;
            float4 av = make_float4(0.f, 0.f, 0.f, 0.f);
            if (ar < M) {
                av = *reinterpret_cast<const float4*>(A + (long long)ar * K + k0 + a_k);
                if (TRANS_A) {
                    float di = dinv[ar];
                    float4 bb = *reinterpret_cast<const float4*>(tbias + k0 + a_k);
                    av.x = fmaxf(fmaf(di, av.x, bb.x), 0.f);
                    av.y = fmaxf(fmaf(di, av.y, bb.y), 0.f);
                    av.z = fmaxf(fmaf(di, av.z, bb.z), 0.f);
                    av.w = fmaxf(fmaf(di, av.w, bb.w), 0.f);
                }
            }
            As[a_k + 0][arl] = av.x;
            As[a_k + 1][arl] = av.y;
            As[a_k + 2][arl] = av.z;
            As[a_k + 3][arl] = av.w;
        }
        #pragma unroll
        for (int s = 0; s < BK / ROWS_PER; s++) {
            int br = b_row0 + s * ROWS_PER;
            float4 bv = *reinterpret_cast<const float4*>(B + (long long)(k0 + br) * Nc + col0 + b_col);
            *reinterpret_cast<float4*>(&Bs[br][b_col]) = bv;
        }
        __syncthreads();

        #pragma unroll
        for (int k = 0; k < BK; k++) {
            float a[TM], b[TN];
            #pragma unroll
            for (int i = 0; i < TM / 4; i++) {
                float4 a4 = *reinterpret_cast<const float4*>(&As[k][m0 + i * 4]);
                a[i*4+0]=a4.x; a[i*4+1]=a4.y; a[i*4+2]=a4.z; a[i*4+3]=a4.w;
            }
            #pragma unroll
            for (int j = 0; j < TN / 4; j++) {
                float4 b4 = *reinterpret_cast<const float4*>(&Bs[k][n0 + j * 4]);
                b[j*4+0]=b4.x; b[j*4+1]=b4.y; b[j*4+2]=b4.z; b[j*4+3]=b4.w;
            }
            #pragma unroll
            for (int i = 0; i < TM; i++)
                #pragma unroll
                for (int j = 0; j < TN; j++)
                    acc[i][j] = fmaf(a[i], b[j], acc[i][j]);
        }
        __syncthreads();
    }

    #pragma unroll
    for (int i = 0; i < TM; i++) {
        int r = row0 + m0 + i;
        if (r < M) {
            float s = dinv[r];
            #pragma unroll
            for (int j = 0; j < TN / 4; j++) {
                float4 v = make_float4(s * acc[i][j*4+0], s * acc[i][j*4+1],
                                       s * acc[i][j*4+2], s * acc[i][j*4+3]);
                long long off = (long long)r * Nc + col0 + n0 + j * 4;
                *reinterpret_cast<float4*>(C1 + off) = v;
                *reinterpret_cast<float4*>(C2 + off) = v;
            }
        }
    }
}

// ---------------- edge scatter: acc[dst] += h2[src] (pure) ------------------
template<int LOGC4, int C>
__global__ void scatter_kernel(const float* __restrict__ h2,
                               const int* __restrict__ src, const int* __restrict__ dst,
                               float* __restrict__ acc, int E) {
    const int C4 = 1 << LOGC4;
    long long idx = (long long)blockIdx.x * blockDim.x + threadIdx.x;
    long long total = (long long)E << LOGC4;
    if (idx >= total) return;
    int e = (int)(idx >> LOGC4);
    int c = (int)(idx & (C4 - 1)) * 4;
    int s = src[e];
    int d = dst[e];
    float4 v = *reinterpret_cast<const float4*>(h2 + (long long)s * C + c);
    atomicAdd(reinterpret_cast<float4*>(acc + (long long)d * C + c), v);
}

// ---------------- final fixup: out = b2 + dinv[i]*out -----------------------
__global__ void fixup_kernel(float* __restrict__ out, const float* __restrict__ dinv,
                             const float* __restrict__ b2, int n) {
    const int C4 = OUT_C / 4;
    int idx = blockIdx.x * blockDim.x + threadIdx.x;
    if (idx >= n * C4) return;
    int i = idx / C4;
    int c = (idx % C4) * 4;
    float di = dinv[i];
    float4 v = *reinterpret_cast<float4*>(out + (long long)i * OUT_C + c);
    float4 bb = *reinterpret_cast<const float4*>(b2 + c);
    v.x = fmaf(di, v.x, bb.x); v.y = fmaf(di, v.y, bb.y);
    v.z = fmaf(di, v.z, bb.z); v.w = fmaf(di, v.w, bb.w);
    *reinterpret_cast<float4*>(out + (long long)i * OUT_C + c) = v;
}

// ---------------- launch ----------------
extern "C" void kernel_launch(void* const* d_in, const int* in_sizes, int n_in,
                              void* d_out, int out_size) {
    const float* x  = (const float*)d_in[0];
    const int*   ei = (const int*)  d_in[1];
    const float* W1 = (const float*)d_in[2];
    const float* b1 = (const float*)d_in[3];
    const float* W2 = (const float*)d_in[4];
    const float* b2 = (const float*)d_in[5];
    float* out = (float*)d_out;

    const int E = in_sizes[1] / 2;
    const int* src = ei;
    const int* dst = ei + E;

    float *deg, *dinv, *h2, *acc1, *z2;
    cudaGetSymbolAddress((void**)&deg,  g_deg);
    cudaGetSymbolAddress((void**)&dinv, g_dinv);
    cudaGetSymbolAddress((void**)&h2,   g_h2);
    cudaGetSymbolAddress((void**)&acc1, g_acc1);
    cudaGetSymbolAddress((void**)&z2,   g_z2);

    // 1) normalization
    zero_deg_kernel<<<(NN + 255) / 256, 256>>>(deg, NN);
    count_deg_kernel<<<(E + 255) / 256, 256>>>(dst, deg, E);
    dinv_kernel<<<(NN + 255) / 256, 256>>>(deg, dinv, NN);

    // 2) GEMM1: h2 = dinv * (x @ W1); acc1 initialized to h2 (self-loop term)
    {
        dim3 grid((NN + 127) / 128, HID_C / 64);
        sgemm_fused<128, 64, 8, 4, false><<<grid, 256>>>(
            x, W1, h2, acc1, dinv, nullptr, NN, IN_C, HID_C);
    }
    // 3) scatter layer 1: acc1[dst] += h2[src]
    {
        long long etotal = (long long)E * (HID_C / 4);
        scatter_kernel<5, HID_C><<<(int)((etotal + 255) / 256), 256>>>(h2, src, dst, acc1, E);
    }
    // 4) GEMM2: A = relu(b1 + dinv*acc1); z2 = dinv*(A @ W2); out init = z2
    {
        dim3 grid((NN + 127) / 128, OUT_C / 64);
        sgemm_fused<128, 64, 8, 4, true><<<grid, 256>>>(
            acc1, W2, z2, out, dinv, b1, NN, HID_C, OUT_C);
    }
    // 5) scatter layer 2: out[dst] += z2[src]
    {
        long long etotal = (long long)E * (OUT_C / 4);
        scatter_kernel<4, OUT_C><<<(int)((etotal + 255) / 256), 256>>>(z2, src, dst, out, E);
    }
    // 6) out = b2 + dinv*out
    {
        int total = NN * (OUT_C / 4);
        fixup_kernel<<<(total + 255) / 256, 256>>>(out, dinv, b2, NN);
    }
}

// round 5
// speedup vs baseline: 1.5297x; 1.3508x over previous
#include <cuda_runtime.h>
#include <cuda_bf16.h>

#define NN     50000
#define IN_C   256
#define HID_C  128
#define OUT_C  64
#define E_MAX  800000
#define NB     ((NN + 255) / 256)   // 196 blocks for scan

// ---------------- scratch ----------------
__device__ __align__(16) float g_dinv[NN];
__device__ __align__(16) int   g_degi[NN];
__device__ __align__(16) int   g_row [NN + 1];
__device__ __align__(16) int   g_cur [NN];
__device__ __align__(16) int   g_bsum[NB];
__device__ __align__(16) int   g_csr [E_MAX];
__device__ __align__(16) float g_h2  [NN * HID_C];   // dinv * (x @ W1)
__device__ __align__(16) float g_agg1[NN * HID_C];   // pulled layer-1 sum
__device__ __align__(16) float g_z2  [NN * OUT_C];   // dinv * (relu(...) @ W2)

// ---------------- degree histogram / dinv ----------------
__global__ void zero_degi_kernel(int* deg, int n) {
    int i = blockIdx.x * blockDim.x + threadIdx.x;
    if (i < n) deg[i] = 0;
}
__global__ void count_deg_kernel(const int* __restrict__ dst, int* __restrict__ deg, int E) {
    int e = blockIdx.x * blockDim.x + threadIdx.x;
    if (e < E) atomicAdd(&deg[dst[e]], 1);
}
__global__ void dinv_kernel(const int* __restrict__ deg, float* __restrict__ dinv, int n) {
    int i = blockIdx.x * blockDim.x + threadIdx.x;
    if (i < n) dinv[i] = rsqrtf((float)deg[i] + 1.0f);   // +1 self loop
}

// ---------------- prefix scan (3 kernels) ----------------
__global__ void block_sum_kernel(const int* __restrict__ deg, int* __restrict__ bsum, int n) {
    __shared__ int s[256];
    int i = blockIdx.x * 256 + threadIdx.x;
    s[threadIdx.x] = (i < n) ? deg[i] : 0;
    __syncthreads();
    for (int off = 128; off > 0; off >>= 1) {
        if (threadIdx.x < off) s[threadIdx.x] += s[threadIdx.x + off];
        __syncthreads();
    }
    if (threadIdx.x == 0) bsum[blockIdx.x] = s[0];
}
// single block: exclusive scan of nb (<=256) block sums
__global__ void scan_bsum_kernel(int* __restrict__ bsum, int nb) {
    __shared__ int s[256];
    int t = threadIdx.x;
    s[t] = (t < nb) ? bsum[t] : 0;
    __syncthreads();
    // Hillis-Steele inclusive
    for (int off = 1; off < 256; off <<= 1) {
        int v = (t >= off) ? s[t - off] : 0;
        __syncthreads();
        s[t] += v;
        __syncthreads();
    }
    if (t < nb) bsum[t] = s[t] - ((t < nb) ? 0 : 0) - ( /*exclusive*/ 0 );
    // convert inclusive->exclusive on write:
    if (t < nb) {
        int incl = s[t];
        int excl = incl - ((t < nb) ? ( /*self*/ 0 ) : 0);
        (void)excl;
    }
    __syncthreads();
    if (t < nb) bsum[t] = (t == 0) ? 0 : s[t - 1];
}
__global__ void scan_final_kernel(const int* __restrict__ deg, const int* __restrict__ bsum,
                                  int* __restrict__ row, int* __restrict__ cur, int n) {
    __shared__ int s[256];
    int i = blockIdx.x * 256 + threadIdx.x;
    int v = (i < n) ? deg[i] : 0;
    s[threadIdx.x] = v;
    __syncthreads();
    // inclusive scan in shared
    for (int off = 1; off < 256; off <<= 1) {
        int u = (threadIdx.x >= off) ? s[threadIdx.x - off] : 0;
        __syncthreads();
        s[threadIdx.x] += u;
        __syncthreads();
    }
    if (i < n) {
        int excl = s[threadIdx.x] - v + bsum[blockIdx.x];
        row[i] = excl;
        cur[i] = excl;
        if (i == n - 1) row[n] = excl + v;
    }
}
__global__ void slot_scatter_kernel(const int* __restrict__ src, const int* __restrict__ dst,
                                    int* __restrict__ cur, int* __restrict__ csr, int E) {
    int e = blockIdx.x * blockDim.x + threadIdx.x;
    if (e < E) {
        int pos = atomicAdd(&cur[dst[e]], 1);
        csr[pos] = src[e];
    }
}

// ---------------- SGEMM with fused transforms --------------------------------
// C = op(A) @ B ; op(A)=A or relu(tbias + dinv[r]*A).  Epilogue: C = dinv[r]*acc.
template<int BM, int BN, int TM, int TN, bool TRANS_A>
__global__ void sgemm_fused(const float* __restrict__ A, const float* __restrict__ B,
                            float* __restrict__ C1,
                            const float* __restrict__ dinv, const float* __restrict__ tbias,
                            int M, int K, int Nc) {
    const int BK = 16;
    __shared__ __align__(16) float As[BK][BM];
    __shared__ __align__(16) float Bs[BK][BN];

    const int tid  = threadIdx.x;
    const int row0 = blockIdx.x * BM;
    const int col0 = blockIdx.y * BN;

    const int a_row = tid >> 2;
    const int a_k   = (tid & 3) * 4;
    const int BN4      = BN / 4;
    const int b_col    = (tid % BN4) * 4;
    const int b_row0   = tid / BN4;
    const int ROWS_PER = 256 / BN4;

    const int tx = tid % (BN / TN);
    const int ty = tid / (BN / TN);
    const int m0 = ty * TM;
    const int n0 = tx * TN;

    float acc[TM][TN];
    #pragma unroll
    for (int i = 0; i < TM; i++)
        #pragma unroll
        for (int j = 0; j < TN; j++) acc[i][j] = 0.0f;

    for (int k0 = 0; k0 < K; k0 += BK) {
        #pragma unroll
        for (int s = 0; s < BM / 64; s++) {
            int arl = a_row + s * 64;
            int ar  = row0 + arl;
            float4 av = make_float4(0.f, 0.f, 0.f, 0.f);
            if (ar < M) {
                av = *reinterpret_cast<const float4*>(A + (long long)ar * K + k0 + a_k);
                if (TRANS_A) {
                    float di = dinv[ar];
                    float4 bb = *reinterpret_cast<const float4*>(tbias + k0 + a_k);
                    av.x = fmaxf(fmaf(di, av.x, bb.x), 0.f);
                    av.y = fmaxf(fmaf(di, av.y, bb.y), 0.f);
                    av.z = fmaxf(fmaf(di, av.z, bb.z), 0.f);
                    av.w = fmaxf(fmaf(di, av.w, bb.w), 0.f);
                }
            }
            As[a_k + 0][arl] = av.x;
            As[a_k + 1][arl] = av.y;
            As[a_k + 2][arl] = av.z;
            As[a_k + 3][arl] = av.w;
        }
        #pragma unroll
        for (int s = 0; s < BK / ROWS_PER; s++) {
            int br = b_row0 + s * ROWS_PER;
            float4 bv = *reinterpret_cast<const float4*>(B + (long long)(k0 + br) * Nc + col0 + b_col);
            *reinterpret_cast<float4*>(&Bs[br][b_col]) = bv;
        }
        __syncthreads();

        #pragma unroll
        for (int k = 0; k < BK; k++) {
            float a[TM], b[TN];
            #pragma unroll
            for (int i = 0; i < TM / 4; i++) {
                float4 a4 = *reinterpret_cast<const float4*>(&As[k][m0 + i * 4]);
                a[i*4+0]=a4.x; a[i*4+1]=a4.y; a[i*4+2]=a4.z; a[i*4+3]=a4.w;
            }
            #pragma unroll
            for (int j = 0; j < TN / 4; j++) {
                float4 b4 = *reinterpret_cast<const float4*>(&Bs[k][n0 + j * 4]);
                b[j*4+0]=b4.x; b[j*4+1]=b4.y; b[j*4+2]=b4.z; b[j*4+3]=b4.w;
            }
            #pragma unroll
            for (int i = 0; i < TM; i++)
                #pragma unroll
                for (int j = 0; j < TN; j++)
                    acc[i][j] = fmaf(a[i], b[j], acc[i][j]);
        }
        __syncthreads();
    }

    #pragma unroll
    for (int i = 0; i < TM; i++) {
        int r = row0 + m0 + i;
        if (r < M) {
            float s = dinv[r];
            #pragma unroll
            for (int j = 0; j < TN / 4; j++) {
                float4 v = make_float4(s * acc[i][j*4+0], s * acc[i][j*4+1],
                                       s * acc[i][j*4+2], s * acc[i][j*4+3]);
                *reinterpret_cast<float4*>(C1 + (long long)r * Nc + col0 + n0 + j * 4) = v;
            }
        }
    }
}

// ---------------- pull layer 1: agg1[d] = h2[d] + sum_{s in N(d)} h2[s] -------
// one warp per node, lane owns float4 channel chunk (C=128)
__global__ void pull128_kernel(const float* __restrict__ h2,
                               const int* __restrict__ row, const int* __restrict__ csr,
                               float* __restrict__ agg, int n) {
    int gw = (blockIdx.x * blockDim.x + threadIdx.x) >> 5;
    int lane = threadIdx.x & 31;
    if (gw >= n) return;
    long long base = (long long)gw * HID_C + lane * 4;
    float4 a = *reinterpret_cast<const float4*>(h2 + base);   // self loop
    int beg = row[gw], end = row[gw + 1];
    int j = beg;
    // unroll by 2 for MLP
    for (; j + 1 < end; j += 2) {
        int s0 = csr[j], s1 = csr[j + 1];
        float4 v0 = *reinterpret_cast<const float4*>(h2 + (long long)s0 * HID_C + lane * 4);
        float4 v1 = *reinterpret_cast<const float4*>(h2 + (long long)s1 * HID_C + lane * 4);
        a.x += v0.x + v1.x; a.y += v0.y + v1.y;
        a.z += v0.z + v1.z; a.w += v0.w + v1.w;
    }
    if (j < end) {
        int s0 = csr[j];
        float4 v0 = *reinterpret_cast<const float4*>(h2 + (long long)s0 * HID_C + lane * 4);
        a.x += v0.x; a.y += v0.y; a.z += v0.z; a.w += v0.w;
    }
    *reinterpret_cast<float4*>(agg + base) = a;
}

// ---------------- pull layer 2: out[d] = b2 + dinv[d]*(z2[d] + sum z2[s]) ----
// one warp per node, lane owns float2 chunk (C=64)
__global__ void pull64_kernel(const float* __restrict__ z2,
                              const int* __restrict__ row, const int* __restrict__ csr,
                              const float* __restrict__ dinv, const float* __restrict__ b2,
                              float* __restrict__ out, int n) {
    int gw = (blockIdx.x * blockDim.x + threadIdx.x) >> 5;
    int lane = threadIdx.x & 31;
    if (gw >= n) return;
    long long base = (long long)gw * OUT_C + lane * 2;
    float2 a = *reinterpret_cast<const float2*>(z2 + base);   // self loop
    int beg = row[gw], end = row[gw + 1];
    int j = beg;
    for (; j + 1 < end; j += 2) {
        int s0 = csr[j], s1 = csr[j + 1];
        float2 v0 = *reinterpret_cast<const float2*>(z2 + (long long)s0 * OUT_C + lane * 2);
        float2 v1 = *reinterpret_cast<const float2*>(z2 + (long long)s1 * OUT_C + lane * 2);
        a.x += v0.x + v1.x; a.y += v0.y + v1.y;
    }
    if (j < end) {
        int s0 = csr[j];
        float2 v0 = *reinterpret_cast<const float2*>(z2 + (long long)s0 * OUT_C + lane * 2);
        a.x += v0.x; a.y += v0.y;
    }
    float di = dinv[gw];
    float2 bb = *reinterpret_cast<const float2*>(b2 + lane * 2);
    float2 o = make_float2(fmaf(di, a.x, bb.x), fmaf(di, a.y, bb.y));
    *reinterpret_cast<float2*>(out + base) = o;
}

// ---------------- launch ----------------
extern "C" void kernel_launch(void* const* d_in, const int* in_sizes, int n_in,
                              void* d_out, int out_size) {
    const float* x  = (const float*)d_in[0];
    const int*   ei = (const int*)  d_in[1];
    const float* W1 = (const float*)d_in[2];
    const float* b1 = (const float*)d_in[3];
    const float* W2 = (const float*)d_in[4];
    const float* b2 = (const float*)d_in[5];
    float* out = (float*)d_out;

    const int E = in_sizes[1] / 2;
    const int* src = ei;
    const int* dst = ei + E;

    float *dinv, *h2, *agg1, *z2;
    int *degi, *row, *cur, *bsum, *csr;
    cudaGetSymbolAddress((void**)&dinv, g_dinv);
    cudaGetSymbolAddress((void**)&degi, g_degi);
    cudaGetSymbolAddress((void**)&row,  g_row);
    cudaGetSymbolAddress((void**)&cur,  g_cur);
    cudaGetSymbolAddress((void**)&bsum, g_bsum);
    cudaGetSymbolAddress((void**)&csr,  g_csr);
    cudaGetSymbolAddress((void**)&h2,   g_h2);
    cudaGetSymbolAddress((void**)&agg1, g_agg1);
    cudaGetSymbolAddress((void**)&z2,   g_z2);

    // 1) degree histogram + dinv + CSR build
    zero_degi_kernel<<<(NN + 255) / 256, 256>>>(degi, NN);
    count_deg_kernel<<<(E + 255) / 256, 256>>>(dst, degi, E);
    dinv_kernel<<<(NN + 255) / 256, 256>>>(degi, dinv, NN);
    block_sum_kernel<<<NB, 256>>>(degi, bsum, NN);
    scan_bsum_kernel<<<1, 256>>>(bsum, NB);
    scan_final_kernel<<<NB, 256>>>(degi, bsum, row, cur, NN);
    slot_scatter_kernel<<<(E + 255) / 256, 256>>>(src, dst, cur, csr, E);

    // 2) GEMM1: h2 = dinv * (x @ W1)
    {
        dim3 grid((NN + 127) / 128, HID_C / 64);
        sgemm_fused<128, 64, 8, 4, false><<<grid, 256>>>(
            x, W1, h2, dinv, nullptr, NN, IN_C, HID_C);
    }
    // 3) pull layer 1: agg1 = h2[self] + sum of in-neighbors
    pull128_kernel<<<(NN * 32 + 255) / 256, 256>>>(h2, row, csr, agg1, NN);

    // 4) GEMM2: A = relu(b1 + dinv*agg1); z2 = dinv*(A @ W2)
    {
        dim3 grid((NN + 127) / 128, OUT_C / 64);
        sgemm_fused<128, 64, 8, 4, true><<<grid, 256>>>(
            agg1, W2, z2, dinv, b1, NN, HID_C, OUT_C);
    }
    // 5) pull layer 2 + bias fixup fused
    pull64_kernel<<<(NN * 32 + 255) / 256, 256>>>(z2, row, csr, dinv, b2, out, NN);
}

// round 7
// speedup vs baseline: 2.2716x; 1.4850x over previous
#include <cuda_runtime.h>
#include <cuda_bf16.h>
#include <cstdint>

#define NN     50000
#define IN_C   256
#define HID_C  128
#define OUT_C  64
#define E_MAX  800000
#define NB     ((NN + 255) / 256)

// ---------------- scratch ----------------
__device__ __align__(16) float g_dinv[NN];
__device__ __align__(16) int   g_degi[NN];
__device__ __align__(16) int   g_row [NN + 1];
__device__ __align__(16) int   g_cur [NN];
__device__ __align__(16) int   g_bsum[NB];
__device__ __align__(16) int   g_csr [E_MAX];
__device__ __align__(16) float g_h2  [NN * HID_C];
__device__ __align__(16) float g_agg1[NN * HID_C];
__device__ __align__(16) float g_z2  [NN * OUT_C];
// transposed bf16 hi/lo weights: [N, K] (k contiguous per n == mma "col" B layout)
__device__ __align__(16) __nv_bfloat16 g_w1hi[HID_C * IN_C];
__device__ __align__(16) __nv_bfloat16 g_w1lo[HID_C * IN_C];
__device__ __align__(16) __nv_bfloat16 g_w2hi[OUT_C * HID_C];
__device__ __align__(16) __nv_bfloat16 g_w2lo[OUT_C * HID_C];

// ---------------- degree / dinv / CSR ----------------
__global__ void zero_degi_kernel(int* deg, int n) {
    int i = blockIdx.x * blockDim.x + threadIdx.x;
    if (i < n) deg[i] = 0;
}
__global__ void count_deg_kernel(const int* __restrict__ dst, int* __restrict__ deg, int E) {
    int e = blockIdx.x * blockDim.x + threadIdx.x;
    if (e < E) atomicAdd(&deg[dst[e]], 1);
}
__global__ void dinv_kernel(const int* __restrict__ deg, float* __restrict__ dinv, int n) {
    int i = blockIdx.x * blockDim.x + threadIdx.x;
    if (i < n) dinv[i] = rsqrtf((float)deg[i] + 1.0f);
}
__global__ void block_sum_kernel(const int* __restrict__ deg, int* __restrict__ bsum, int n) {
    __shared__ int s[256];
    int i = blockIdx.x * 256 + threadIdx.x;
    s[threadIdx.x] = (i < n) ? deg[i] : 0;
    __syncthreads();
    for (int off = 128; off > 0; off >>= 1) {
        if (threadIdx.x < off) s[threadIdx.x] += s[threadIdx.x + off];
        __syncthreads();
    }
    if (threadIdx.x == 0) bsum[blockIdx.x] = s[0];
}
__global__ void scan_bsum_kernel(int* __restrict__ bsum, int nb) {
    __shared__ int s[256];
    int t = threadIdx.x;
    s[t] = (t < nb) ? bsum[t] : 0;
    __syncthreads();
    for (int off = 1; off < 256; off <<= 1) {
        int v = (t >= off) ? s[t - off] : 0;
        __syncthreads();
        s[t] += v;
        __syncthreads();
    }
    if (t < nb) bsum[t] = (t == 0) ? 0 : s[t - 1];
}
__global__ void scan_final_kernel(const int* __restrict__ deg, const int* __restrict__ bsum,
                                  int* __restrict__ row, int* __restrict__ cur, int n) {
    __shared__ int s[256];
    int i = blockIdx.x * 256 + threadIdx.x;
    int v = (i < n) ? deg[i] : 0;
    s[threadIdx.x] = v;
    __syncthreads();
    for (int off = 1; off < 256; off <<= 1) {
        int u = (threadIdx.x >= off) ? s[threadIdx.x - off] : 0;
        __syncthreads();
        s[threadIdx.x] += u;
        __syncthreads();
    }
    if (i < n) {
        int excl = s[threadIdx.x] - v + bsum[blockIdx.x];
        row[i] = excl;
        cur[i] = excl;
        if (i == n - 1) row[n] = excl + v;
    }
}
__global__ void slot_scatter_kernel(const int* __restrict__ src, const int* __restrict__ dst,
                                    int* __restrict__ cur, int* __restrict__ csr, int E) {
    int e = blockIdx.x * blockDim.x + threadIdx.x;
    if (e < E) {
        int pos = atomicAdd(&cur[dst[e]], 1);
        csr[pos] = src[e];
    }
}

// ---------------- weight conversion: W[K,N] fp32 -> Whi/Wlo [N,K] bf16 -------
__global__ void convert_w_kernel(const float* __restrict__ W,
                                 __nv_bfloat16* __restrict__ Whi, __nv_bfloat16* __restrict__ Wlo,
                                 int K, int Nc) {
    int idx = blockIdx.x * blockDim.x + threadIdx.x;
    if (idx >= K * Nc) return;
    int n = idx / K, k = idx % K;
    float v = W[(long long)k * Nc + n];
    __nv_bfloat16 hi = __float2bfloat16_rn(v);
    float r = v - __bfloat162float(hi);
    Whi[idx] = hi;
    Wlo[idx] = __float2bfloat16_rn(r);
}

// ---------------- mma.sync helper -------------------------------------------
__device__ __forceinline__ void mma16816(float c[4], const uint32_t a[4], const uint32_t b[2]) {
    asm volatile(
        "mma.sync.aligned.m16n8k16.row.col.f32.bf16.bf16.f32 "
        "{%0,%1,%2,%3}, {%4,%5,%6,%7}, {%8,%9}, {%0,%1,%2,%3};"
        : "+f"(c[0]), "+f"(c[1]), "+f"(c[2]), "+f"(c[3])
        : "r"(a[0]), "r"(a[1]), "r"(a[2]), "r"(a[3]), "r"(b[0]), "r"(b[1]));
}

// ---------------- bf16x3 HMMA GEMM -------------------------------------------
// C[r][n] = dinv[r] * sum_k op(A)[r][k] * W[k][n]
// op(A)=A (TRANS=false) or relu(bias[k] + dinv[r]*A[r][k]) (TRANS=true)
// BM=128, BN=Nc (128 or 64), BK=64, 8 warps; warp tile 32 x (BN/2).
template<int BN, int KTOT, bool TRANS>
__global__ void __launch_bounds__(256, 2)
mma_gemm(const float* __restrict__ A,
         const __nv_bfloat16* __restrict__ Whi, const __nv_bfloat16* __restrict__ Wlo,
         float* __restrict__ C,
         const float* __restrict__ dinv, const float* __restrict__ bias, int M) {
    const int BM = 128, BK = 64, LD = 72;          // LD: padded bf16 row stride
    const int NW = BN / 2;                          // warp n-width
    const int NT = NW / 8;                          // n-tiles per warp
    // smem layout (bytes)
    const int A_HI = 0;
    const int A_LO = A_HI + BM * LD * 2;
    const int B_HI = A_LO + BM * LD * 2;
    const int B_LO = B_HI + BN * LD * 2;

    extern __shared__ __align__(16) char smem[];
    __nv_bfloat16* as_hi = reinterpret_cast<__nv_bfloat16*>(smem + A_HI);
    __nv_bfloat16* as_lo = reinterpret_cast<__nv_bfloat16*>(smem + A_LO);
    __nv_bfloat16* bs_hi = reinterpret_cast<__nv_bfloat16*>(smem + B_HI);
    __nv_bfloat16* bs_lo = reinterpret_cast<__nv_bfloat16*>(smem + B_LO);

    const int tid  = threadIdx.x;
    const int wid  = tid >> 5;
    const int lane = tid & 31;
    const int g    = lane >> 2;     // group id (0..7)
    const int t    = lane & 3;      // thread in group
    const int wm   = wid & 3;       // m-group (32 rows each)
    const int wn   = wid >> 2;      // n-group (NW cols each)
    const int row0 = blockIdx.x * BM;

    float acc[2][NT > 0 ? NT : 1][4];
    #pragma unroll
    for (int mt = 0; mt < 2; mt++)
        #pragma unroll
        for (int nt = 0; nt < NT; nt++)
            #pragma unroll
            for (int q = 0; q < 4; q++) acc[mt][nt][q] = 0.0f;

    for (int kc = 0; kc < KTOT; kc += BK) {
        // ---- fill A tiles (fp32 -> bf16 hi/lo) ----
        #pragma unroll
        for (int it = 0; it < (BM * BK / 4) / 256; it++) {
            int idx = tid + it * 256;
            int row = idx >> 4;
            int k4  = (idx & 15) * 4;
            int gr  = row0 + row;
            float4 v = make_float4(0.f, 0.f, 0.f, 0.f);
            if (gr < M) {
                v = *reinterpret_cast<const float4*>(A + (long long)gr * KTOT + kc + k4);
                if (TRANS) {
                    float di = dinv[gr];
                    float4 bb = *reinterpret_cast<const float4*>(bias + kc + k4);
                    v.x = fmaxf(fmaf(di, v.x, bb.x), 0.f);
                    v.y = fmaxf(fmaf(di, v.y, bb.y), 0.f);
                    v.z = fmaxf(fmaf(di, v.z, bb.z), 0.f);
                    v.w = fmaxf(fmaf(di, v.w, bb.w), 0.f);
                }
            }
            __nv_bfloat162 h01 = __floats2bfloat162_rn(v.x, v.y);
            __nv_bfloat162 h23 = __floats2bfloat162_rn(v.z, v.w);
            float lx = v.x - __bfloat162float(__low2bfloat16(h01));
            float ly = v.y - __bfloat162float(__high2bfloat16(h01));
            float lz = v.z - __bfloat162float(__low2bfloat16(h23));
            float lw = v.w - __bfloat162float(__high2bfloat16(h23));
            __nv_bfloat162 l01 = __floats2bfloat162_rn(lx, ly);
            __nv_bfloat162 l23 = __floats2bfloat162_rn(lz, lw);
            int off = row * LD + k4;
            *reinterpret_cast<uint2*>(as_hi + off) =
                make_uint2(*reinterpret_cast<uint32_t*>(&h01), *reinterpret_cast<uint32_t*>(&h23));
            *reinterpret_cast<uint2*>(as_lo + off) =
                make_uint2(*reinterpret_cast<uint32_t*>(&l01), *reinterpret_cast<uint32_t*>(&l23));
        }
        // ---- fill B tiles (bf16 [N,K] slice) ----
        #pragma unroll
        for (int it = 0; it < (BN * BK / 4) / 256; it++) {
            int idx = tid + it * 256;
            int n  = idx >> 4;
            int k4 = (idx & 15) * 4;
            uint2 wh = *reinterpret_cast<const uint2*>(Whi + (long long)n * KTOT + kc + k4);
            uint2 wl = *reinterpret_cast<const uint2*>(Wlo + (long long)n * KTOT + kc + k4);
            int off = n * LD + k4;
            *reinterpret_cast<uint2*>(bs_hi + off) = wh;
            *reinterpret_cast<uint2*>(bs_lo + off) = wl;
        }
        __syncthreads();

        // ---- compute ----
        #pragma unroll
        for (int kk = 0; kk < BK; kk += 16) {
            uint32_t ah[2][4], al[2][4];
            #pragma unroll
            for (int mt = 0; mt < 2; mt++) {
                int ar = wm * 32 + mt * 16;
                int o00 = (ar + g) * LD + kk + 2 * t;
                int o10 = (ar + 8 + g) * LD + kk + 2 * t;
                ah[mt][0] = *reinterpret_cast<const uint32_t*>(as_hi + o00);
                ah[mt][1] = *reinterpret_cast<const uint32_t*>(as_hi + o10);
                ah[mt][2] = *reinterpret_cast<const uint32_t*>(as_hi + o00 + 8);
                ah[mt][3] = *reinterpret_cast<const uint32_t*>(as_hi + o10 + 8);
                al[mt][0] = *reinterpret_cast<const uint32_t*>(as_lo + o00);
                al[mt][1] = *reinterpret_cast<const uint32_t*>(as_lo + o10);
                al[mt][2] = *reinterpret_cast<const uint32_t*>(as_lo + o00 + 8);
                al[mt][3] = *reinterpret_cast<const uint32_t*>(as_lo + o10 + 8);
            }
            #pragma unroll
            for (int nt = 0; nt < NT; nt++) {
                int bn = wn * NW + nt * 8 + g;
                int ob = bn * LD + kk + 2 * t;
                uint32_t bh[2], bl[2];
                bh[0] = *reinterpret_cast<const uint32_t*>(bs_hi + ob);
                bh[1] = *reinterpret_cast<const uint32_t*>(bs_hi + ob + 8);
                bl[0] = *reinterpret_cast<const uint32_t*>(bs_lo + ob);
                bl[1] = *reinterpret_cast<const uint32_t*>(bs_lo + ob + 8);
                #pragma unroll
                for (int mt = 0; mt < 2; mt++) {
                    mma16816(acc[mt][nt], ah[mt], bh);
                    mma16816(acc[mt][nt], ah[mt], bl);
                    mma16816(acc[mt][nt], al[mt], bh);
                }
            }
        }
        __syncthreads();
    }

    // ---- epilogue: scale by dinv, store ----
    #pragma unroll
    for (int mt = 0; mt < 2; mt++) {
        int r0 = row0 + wm * 32 + mt * 16 + g;
        int r1 = r0 + 8;
        float s0 = (r0 < M) ? dinv[r0] : 0.0f;
        float s1 = (r1 < M) ? dinv[r1] : 0.0f;
        #pragma unroll
        for (int nt = 0; nt < NT; nt++) {
            int cc = wn * NW + nt * 8 + 2 * t;
            if (r0 < M)
                *reinterpret_cast<float2*>(C + (long long)r0 * BN + cc) =
                    make_float2(s0 * acc[mt][nt][0], s0 * acc[mt][nt][1]);
            if (r1 < M)
                *reinterpret_cast<float2*>(C + (long long)r1 * BN + cc) =
                    make_float2(s1 * acc[mt][nt][2], s1 * acc[mt][nt][3]);
        }
    }
}

// ---------------- pull layer 1: agg1[d] = h2[d] + sum h2[src] ----------------
__global__ void pull128_kernel(const float* __restrict__ h2,
                               const int* __restrict__ row, const int* __restrict__ csr,
                               float* __restrict__ agg, int n) {
    int gw = (blockIdx.x * blockDim.x + threadIdx.x) >> 5;
    int lane = threadIdx.x & 31;
    if (gw >= n) return;
    long long base = (long long)gw * HID_C + lane * 4;
    float4 a = *reinterpret_cast<const float4*>(h2 + base);
    int beg = row[gw], end = row[gw + 1];
    int j = beg;
    for (; j + 1 < end; j += 2) {
        int s0 = csr[j], s1 = csr[j + 1];
        float4 v0 = *reinterpret_cast<const float4*>(h2 + (long long)s0 * HID_C + lane * 4);
        float4 v1 = *reinterpret_cast<const float4*>(h2 + (long long)s1 * HID_C + lane * 4);
        a.x += v0.x + v1.x; a.y += v0.y + v1.y;
        a.z += v0.z + v1.z; a.w += v0.w + v1.w;
    }
    if (j < end) {
        int s0 = csr[j];
        float4 v0 = *reinterpret_cast<const float4*>(h2 + (long long)s0 * HID_C + lane * 4);
        a.x += v0.x; a.y += v0.y; a.z += v0.z; a.w += v0.w;
    }
    *reinterpret_cast<float4*>(agg + base) = a;
}

// ---------------- pull layer 2: out = b2 + dinv*(z2[d] + sum z2[src]) --------
__global__ void pull64_kernel(const float* __restrict__ z2,
                              const int* __restrict__ row, const int* __restrict__ csr,
                              const float* __restrict__ dinv, const float* __restrict__ b2,
                              float* __restrict__ out, int n) {
    int gw = (blockIdx.x * blockDim.x + threadIdx.x) >> 5;
    int lane = threadIdx.x & 31;
    if (gw >= n) return;
    long long base = (long long)gw * OUT_C + lane * 2;
    float2 a = *reinterpret_cast<const float2*>(z2 + base);
    int beg = row[gw], end = row[gw + 1];
    int j = beg;
    for (; j + 1 < end; j += 2) {
        int s0 = csr[j], s1 = csr[j + 1];
        float2 v0 = *reinterpret_cast<const float2*>(z2 + (long long)s0 * OUT_C + lane * 2);
        float2 v1 = *reinterpret_cast<const float2*>(z2 + (long long)s1 * OUT_C + lane * 2);
        a.x += v0.x + v1.x; a.y += v0.y + v1.y;
    }
    if (j < end) {
        int s0 = csr[j];
        float2 v0 = *reinterpret_cast<const float2*>(z2 + (long long)s0 * OUT_C + lane * 2);
        a.x += v0.x; a.y += v0.y;
    }
    float di = dinv[gw];
    float2 bb = *reinterpret_cast<const float2*>(b2 + lane * 2);
    *reinterpret_cast<float2*>(out + base) =
        make_float2(fmaf(di, a.x, bb.x), fmaf(di, a.y, bb.y));
}

// ---------------- launch ----------------
extern "C" void kernel_launch(void* const* d_in, const int* in_sizes, int n_in,
                              void* d_out, int out_size) {
    const float* x  = (const float*)d_in[0];
    const int*   ei = (const int*)  d_in[1];
    const float* W1 = (const float*)d_in[2];
    const float* b1 = (const float*)d_in[3];
    const float* W2 = (const float*)d_in[4];
    const float* b2 = (const float*)d_in[5];
    float* out = (float*)d_out;

    const int E = in_sizes[1] / 2;
    const int* src = ei;
    const int* dst = ei + E;

    float *dinv, *h2, *agg1, *z2;
    int *degi, *row, *cur, *bsum, *csr;
    __nv_bfloat16 *w1hi, *w1lo, *w2hi, *w2lo;
    cudaGetSymbolAddress((void**)&dinv, g_dinv);
    cudaGetSymbolAddress((void**)&degi, g_degi);
    cudaGetSymbolAddress((void**)&row,  g_row);
    cudaGetSymbolAddress((void**)&cur,  g_cur);
    cudaGetSymbolAddress((void**)&bsum, g_bsum);
    cudaGetSymbolAddress((void**)&csr,  g_csr);
    cudaGetSymbolAddress((void**)&h2,   g_h2);
    cudaGetSymbolAddress((void**)&agg1, g_agg1);
    cudaGetSymbolAddress((void**)&z2,   g_z2);
    cudaGetSymbolAddress((void**)&w1hi, g_w1hi);
    cudaGetSymbolAddress((void**)&w1lo, g_w1lo);
    cudaGetSymbolAddress((void**)&w2hi, g_w2hi);
    cudaGetSymbolAddress((void**)&w2lo, g_w2lo);

    const int LD = 72;
    const int SMEM1 = 2 * 128 * LD * 2 + 2 * 128 * LD * 2;   // 73728 B
    const int SMEM2 = 2 * 128 * LD * 2 + 2 * 64 * LD * 2;    // 55296 B
    cudaFuncSetAttribute(mma_gemm<HID_C, IN_C, false>,
                         cudaFuncAttributeMaxDynamicSharedMemorySize, SMEM1);
    cudaFuncSetAttribute(mma_gemm<OUT_C, HID_C, true>,
                         cudaFuncAttributeMaxDynamicSharedMemorySize, SMEM2);

    // 1) degrees + dinv + CSR
    zero_degi_kernel<<<(NN + 255) / 256, 256>>>(degi, NN);
    count_deg_kernel<<<(E + 255) / 256, 256>>>(dst, degi, E);
    dinv_kernel<<<(NN + 255) / 256, 256>>>(degi, dinv, NN);
    block_sum_kernel<<<NB, 256>>>(degi, bsum, NN);
    scan_bsum_kernel<<<1, 256>>>(bsum, NB);
    scan_final_kernel<<<NB, 256>>>(degi, bsum, row, cur, NN);
    slot_scatter_kernel<<<(E + 255) / 256, 256>>>(src, dst, cur, csr, E);

    // 2) weight conversion (transposed bf16 hi/lo)
    convert_w_kernel<<<(IN_C * HID_C + 255) / 256, 256>>>(W1, w1hi, w1lo, IN_C, HID_C);
    convert_w_kernel<<<(HID_C * OUT_C + 255) / 256, 256>>>(W2, w2hi, w2lo, HID_C, OUT_C);

    // 3) GEMM1 (HMMA bf16x3): h2 = dinv * (x @ W1)
    mma_gemm<HID_C, IN_C, false><<<(NN + 127) / 128, 256, SMEM1>>>(
        x, w1hi, w1lo, h2, dinv, nullptr, NN);

    // 4) pull layer 1
    pull128_kernel<<<(NN * 32 + 255) / 256, 256>>>(h2, row, csr, agg1, NN);

    // 5) GEMM2 (HMMA bf16x3): z2 = dinv * (relu(b1 + dinv*agg1) @ W2)
    mma_gemm<OUT_C, HID_C, true><<<(NN + 127) / 128, 256, SMEM2>>>(
        agg1, w2hi, w2lo, z2, dinv, b1, NN);

    // 6) pull layer 2 + bias
    pull64_kernel<<<(NN * 32 + 255) / 256, 256>>>(z2, row, csr, dinv, b2, out, NN);
}

// round 8
// speedup vs baseline: 2.3674x; 1.0422x over previous
#include <cuda_runtime.h>
#include <cuda_bf16.h>
#include <cstdint>

#define NN     50000
#define IN_C   256
#define HID_C  128
#define OUT_C  64
#define E_MAX  800000
#define NB     ((NN + 255) / 256)   // 196 scan blocks

// ---------------- scratch ----------------
__device__ __align__(16) float g_dinv[NN];
__device__ __align__(16) int   g_degi[NN];
__device__ __align__(16) int   g_row [NN + 1];
__device__ __align__(16) int   g_cur [NN];
__device__ __align__(16) unsigned long long g_desc[NB];   // lookback descriptors
__device__ __align__(16) int   g_csr [E_MAX];
__device__ __align__(16) float g_h2  [NN * HID_C];
__device__ __align__(16) float g_agg1[NN * HID_C];
__device__ __align__(16) float g_z2  [NN * OUT_C];
__device__ __align__(16) __nv_bfloat16 g_w1hi[HID_C * IN_C];
__device__ __align__(16) __nv_bfloat16 g_w1lo[HID_C * IN_C];
__device__ __align__(16) __nv_bfloat16 g_w2hi[OUT_C * HID_C];
__device__ __align__(16) __nv_bfloat16 g_w2lo[OUT_C * HID_C];

// ---------------- prep: zero degi/desc + convert both weight matrices --------
// W[K,N] fp32 -> Whi/Wlo [N,K] bf16 (k-contiguous == mma "col" B layout)
__global__ void prep_kernel(const float* __restrict__ W1, const float* __restrict__ W2,
                            int* __restrict__ degi, unsigned long long* __restrict__ desc,
                            __nv_bfloat16* __restrict__ w1hi, __nv_bfloat16* __restrict__ w1lo,
                            __nv_bfloat16* __restrict__ w2hi, __nv_bfloat16* __restrict__ w2lo) {
    const int W1N = IN_C * HID_C;       // 32768
    const int W2N = HID_C * OUT_C;      // 8192
    const int B0 = NN;                  // desc base
    const int B1 = NN + NB;             // w1 base
    const int B2 = B1 + W1N;            // w2 base
    int idx = blockIdx.x * blockDim.x + threadIdx.x;
    if (idx < NN) {
        degi[idx] = 0;
    } else if (idx < B1) {
        desc[idx - B0] = 0ULL;
    } else if (idx < B2) {
        int i = idx - B1;
        int n = i / IN_C, k = i % IN_C;
        float v = W1[(long long)k * HID_C + n];
        __nv_bfloat16 hi = __float2bfloat16_rn(v);
        w1hi[i] = hi;
        w1lo[i] = __float2bfloat16_rn(v - __bfloat162float(hi));
    } else if (idx < B2 + W2N) {
        int i = idx - B2;
        int n = i / HID_C, k = i % HID_C;
        float v = W2[(long long)k * OUT_C + n];
        __nv_bfloat16 hi = __float2bfloat16_rn(v);
        w2hi[i] = hi;
        w2lo[i] = __float2bfloat16_rn(v - __bfloat162float(hi));
    }
}

__global__ void count_deg_kernel(const int* __restrict__ dst, int* __restrict__ deg, int E) {
    int e = blockIdx.x * blockDim.x + threadIdx.x;
    if (e < E) atomicAdd(&deg[dst[e]], 1);
}

// ---------------- single-pass scan (decoupled lookback) + dinv ---------------
// desc[b]: high32 = state (0 invalid, 1 aggregate, 2 prefix), low32 = value
__global__ void scan_kernel(const int* __restrict__ deg, unsigned long long* __restrict__ desc,
                            int* __restrict__ row, int* __restrict__ cur,
                            float* __restrict__ dinv, int n) {
    __shared__ int s[256];
    __shared__ int s_carry;
    const int bid = blockIdx.x;
    const int t   = threadIdx.x;
    const int i   = bid * 256 + t;
    int v = (i < n) ? deg[i] : 0;
    s[t] = v;
    __syncthreads();
    #pragma unroll
    for (int off = 1; off < 256; off <<= 1) {
        int u = (t >= off) ? s[t - off] : 0;
        __syncthreads();
        s[t] += u;
        __syncthreads();
    }
    int total = s[255];

    // publish aggregate (block 0 publishes final prefix immediately)
    if (t == 0) {
        unsigned long long d = ((unsigned long long)(bid == 0 ? 2u : 1u) << 32)
                             | (unsigned int)total;
        atomicExch(&desc[bid], d);
        if (bid == 0) s_carry = 0;
    }

    // warp-parallel lookback (warp 0)
    if (bid > 0 && t < 32) {
        int carry = 0;
        int j = bid - 1;
        while (true) {
            int jj = j - t;
            unsigned long long d = 0ULL;
            if (jj >= 0) d = *((volatile unsigned long long*)&desc[jj]);
            int st  = (int)(d >> 32);
            int val = (int)(d & 0xffffffffu);
            unsigned ready = __ballot_sync(0xffffffffu, (jj < 0) || st >= 1);
            if (ready != 0xffffffffu) continue;     // some predecessor not ready yet
            unsigned pmask = __ballot_sync(0xffffffffu, (jj >= 0) && st == 2);
            if (pmask) {
                int lp = __ffs(pmask) - 1;          // closest block holding a prefix
                int contrib = (jj >= 0 && t <= lp) ? val : 0;
                #pragma unroll
                for (int o = 16; o > 0; o >>= 1)
                    contrib += __shfl_down_sync(0xffffffffu, contrib, o);
                carry += __shfl_sync(0xffffffffu, contrib, 0);
                break;
            } else {
                int contrib = (jj >= 0) ? val : 0;
                #pragma unroll
                for (int o = 16; o > 0; o >>= 1)
                    contrib += __shfl_down_sync(0xffffffffu, contrib, o);
                carry += __shfl_sync(0xffffffffu, contrib, 0);
                j -= 32;
                if (j < 0) break;                   // unreachable: block 0 has prefix
            }
        }
        if (t == 0) {
            atomicExch(&desc[bid], (2ULL << 32) | (unsigned int)(carry + total));
            s_carry = carry;
        }
    }
    __syncthreads();
    int carry = s_carry;

    if (i < n) {
        int excl = carry + s[t] - v;
        row[i] = excl;
        cur[i] = excl;
        dinv[i] = rsqrtf((float)v + 1.0f);
        if (i == n - 1) row[n] = excl + v;
    }
}

__global__ void slot_scatter_kernel(const int* __restrict__ src, const int* __restrict__ dst,
                                    int* __restrict__ cur, int* __restrict__ csr, int E) {
    int e = blockIdx.x * blockDim.x + threadIdx.x;
    if (e < E) {
        int pos = atomicAdd(&cur[dst[e]], 1);
        csr[pos] = src[e];
    }
}

// ---------------- mma.sync helper -------------------------------------------
__device__ __forceinline__ void mma16816(float c[4], const uint32_t a[4], const uint32_t b[2]) {
    asm volatile(
        "mma.sync.aligned.m16n8k16.row.col.f32.bf16.bf16.f32 "
        "{%0,%1,%2,%3}, {%4,%5,%6,%7}, {%8,%9}, {%0,%1,%2,%3};"
        : "+f"(c[0]), "+f"(c[1]), "+f"(c[2]), "+f"(c[3])
        : "r"(a[0]), "r"(a[1]), "r"(a[2]), "r"(a[3]), "r"(b[0]), "r"(b[1]));
}

// ---------------- bf16x3 HMMA GEMM (unchanged from R7) -----------------------
template<int BN, int KTOT, bool TRANS>
__global__ void __launch_bounds__(256, 2)
mma_gemm(const float* __restrict__ A,
         const __nv_bfloat16* __restrict__ Whi, const __nv_bfloat16* __restrict__ Wlo,
         float* __restrict__ C,
         const float* __restrict__ dinv, const float* __restrict__ bias, int M) {
    const int BM = 128, BK = 64, LD = 72;
    const int NW = BN / 2;
    const int NT = NW / 8;
    const int A_HI = 0;
    const int A_LO = A_HI + BM * LD * 2;
    const int B_HI = A_LO + BM * LD * 2;
    const int B_LO = B_HI + BN * LD * 2;

    extern __shared__ __align__(16) char smem[];
    __nv_bfloat16* as_hi = reinterpret_cast<__nv_bfloat16*>(smem + A_HI);
    __nv_bfloat16* as_lo = reinterpret_cast<__nv_bfloat16*>(smem + A_LO);
    __nv_bfloat16* bs_hi = reinterpret_cast<__nv_bfloat16*>(smem + B_HI);
    __nv_bfloat16* bs_lo = reinterpret_cast<__nv_bfloat16*>(smem + B_LO);

    const int tid  = threadIdx.x;
    const int wid  = tid >> 5;
    const int lane = tid & 31;
    const int g    = lane >> 2;
    const int t    = lane & 3;
    const int wm   = wid & 3;
    const int wn   = wid >> 2;
    const int row0 = blockIdx.x * BM;

    float acc[2][NT > 0 ? NT : 1][4];
    #pragma unroll
    for (int mt = 0; mt < 2; mt++)
        #pragma unroll
        for (int nt = 0; nt < NT; nt++)
            #pragma unroll
            for (int q = 0; q < 4; q++) acc[mt][nt][q] = 0.0f;

    for (int kc = 0; kc < KTOT; kc += BK) {
        #pragma unroll
        for (int it = 0; it < (BM * BK / 4) / 256; it++) {
            int idx = tid + it * 256;
            int row = idx >> 4;
            int k4  = (idx & 15) * 4;
            int gr  = row0 + row;
            float4 v = make_float4(0.f, 0.f, 0.f, 0.f);
            if (gr < M) {
                v = *reinterpret_cast<const float4*>(A + (long long)gr * KTOT + kc + k4);
                if (TRANS) {
                    float di = dinv[gr];
                    float4 bb = *reinterpret_cast<const float4*>(bias + kc + k4);
                    v.x = fmaxf(fmaf(di, v.x, bb.x), 0.f);
                    v.y = fmaxf(fmaf(di, v.y, bb.y), 0.f);
                    v.z = fmaxf(fmaf(di, v.z, bb.z), 0.f);
                    v.w = fmaxf(fmaf(di, v.w, bb.w), 0.f);
                }
            }
            __nv_bfloat162 h01 = __floats2bfloat162_rn(v.x, v.y);
            __nv_bfloat162 h23 = __floats2bfloat162_rn(v.z, v.w);
            float lx = v.x - __bfloat162float(__low2bfloat16(h01));
            float ly = v.y - __bfloat162float(__high2bfloat16(h01));
            float lz = v.z - __bfloat162float(__low2bfloat16(h23));
            float lw = v.w - __bfloat162float(__high2bfloat16(h23));
            __nv_bfloat162 l01 = __floats2bfloat162_rn(lx, ly);
            __nv_bfloat162 l23 = __floats2bfloat162_rn(lz, lw);
            int off = row * LD + k4;
            *reinterpret_cast<uint2*>(as_hi + off) =
                make_uint2(*reinterpret_cast<uint32_t*>(&h01), *reinterpret_cast<uint32_t*>(&h23));
            *reinterpret_cast<uint2*>(as_lo + off) =
                make_uint2(*reinterpret_cast<uint32_t*>(&l01), *reinterpret_cast<uint32_t*>(&l23));
        }
        #pragma unroll
        for (int it = 0; it < (BN * BK / 4) / 256; it++) {
            int idx = tid + it * 256;
            int n  = idx >> 4;
            int k4 = (idx & 15) * 4;
            uint2 wh = *reinterpret_cast<const uint2*>(Whi + (long long)n * KTOT + kc + k4);
            uint2 wl = *reinterpret_cast<const uint2*>(Wlo + (long long)n * KTOT + kc + k4);
            int off = n * LD + k4;
            *reinterpret_cast<uint2*>(bs_hi + off) = wh;
            *reinterpret_cast<uint2*>(bs_lo + off) = wl;
        }
        __syncthreads();

        #pragma unroll
        for (int kk = 0; kk < BK; kk += 16) {
            uint32_t ah[2][4], al[2][4];
            #pragma unroll
            for (int mt = 0; mt < 2; mt++) {
                int ar = wm * 32 + mt * 16;
                int o00 = (ar + g) * LD + kk + 2 * t;
                int o10 = (ar + 8 + g) * LD + kk + 2 * t;
                ah[mt][0] = *reinterpret_cast<const uint32_t*>(as_hi + o00);
                ah[mt][1] = *reinterpret_cast<const uint32_t*>(as_hi + o10);
                ah[mt][2] = *reinterpret_cast<const uint32_t*>(as_hi + o00 + 8);
                ah[mt][3] = *reinterpret_cast<const uint32_t*>(as_hi + o10 + 8);
                al[mt][0] = *reinterpret_cast<const uint32_t*>(as_lo + o00);
                al[mt][1] = *reinterpret_cast<const uint32_t*>(as_lo + o10);
                al[mt][2] = *reinterpret_cast<const uint32_t*>(as_lo + o00 + 8);
                al[mt][3] = *reinterpret_cast<const uint32_t*>(as_lo + o10 + 8);
            }
            #pragma unroll
            for (int nt = 0; nt < NT; nt++) {
                int bn = wn * NW + nt * 8 + g;
                int ob = bn * LD + kk + 2 * t;
                uint32_t bh[2], bl[2];
                bh[0] = *reinterpret_cast<const uint32_t*>(bs_hi + ob);
                bh[1] = *reinterpret_cast<const uint32_t*>(bs_hi + ob + 8);
                bl[0] = *reinterpret_cast<const uint32_t*>(bs_lo + ob);
                bl[1] = *reinterpret_cast<const uint32_t*>(bs_lo + ob + 8);
                #pragma unroll
                for (int mt = 0; mt < 2; mt++) {
                    mma16816(acc[mt][nt], ah[mt], bh);
                    mma16816(acc[mt][nt], ah[mt], bl);
                    mma16816(acc[mt][nt], al[mt], bh);
                }
            }
        }
        __syncthreads();
    }

    #pragma unroll
    for (int mt = 0; mt < 2; mt++) {
        int r0 = row0 + wm * 32 + mt * 16 + g;
        int r1 = r0 + 8;
        float s0 = (r0 < M) ? dinv[r0] : 0.0f;
        float s1 = (r1 < M) ? dinv[r1] : 0.0f;
        #pragma unroll
        for (int nt = 0; nt < NT; nt++) {
            int cc = wn * NW + nt * 8 + 2 * t;
            if (r0 < M)
                *reinterpret_cast<float2*>(C + (long long)r0 * BN + cc) =
                    make_float2(s0 * acc[mt][nt][0], s0 * acc[mt][nt][1]);
            if (r1 < M)
                *reinterpret_cast<float2*>(C + (long long)r1 * BN + cc) =
                    make_float2(s1 * acc[mt][nt][2], s1 * acc[mt][nt][3]);
        }
    }
}

// ---------------- pull layer 1: agg1[d] = h2[d] + sum h2[src], unroll 4 ------
__global__ void pull128_kernel(const float* __restrict__ h2,
                               const int* __restrict__ row, const int* __restrict__ csr,
                               float* __restrict__ agg, int n) {
    int gw = (blockIdx.x * blockDim.x + threadIdx.x) >> 5;
    int lane = threadIdx.x & 31;
    if (gw >= n) return;
    long long base = (long long)gw * HID_C + lane * 4;
    float4 a = *reinterpret_cast<const float4*>(h2 + base);
    int beg = row[gw], end = row[gw + 1];
    int j = beg;
    for (; j + 3 < end; j += 4) {
        int s0 = csr[j], s1 = csr[j + 1], s2 = csr[j + 2], s3 = csr[j + 3];
        float4 v0 = *reinterpret_cast<const float4*>(h2 + (long long)s0 * HID_C + lane * 4);
        float4 v1 = *reinterpret_cast<const float4*>(h2 + (long long)s1 * HID_C + lane * 4);
        float4 v2 = *reinterpret_cast<const float4*>(h2 + (long long)s2 * HID_C + lane * 4);
        float4 v3 = *reinterpret_cast<const float4*>(h2 + (long long)s3 * HID_C + lane * 4);
        a.x += (v0.x + v1.x) + (v2.x + v3.x);
        a.y += (v0.y + v1.y) + (v2.y + v3.y);
        a.z += (v0.z + v1.z) + (v2.z + v3.z);
        a.w += (v0.w + v1.w) + (v2.w + v3.w);
    }
    for (; j < end; j++) {
        int s0 = csr[j];
        float4 v0 = *reinterpret_cast<const float4*>(h2 + (long long)s0 * HID_C + lane * 4);
        a.x += v0.x; a.y += v0.y; a.z += v0.z; a.w += v0.w;
    }
    *reinterpret_cast<float4*>(agg + base) = a;
}

// ---------------- pull layer 2: out = b2 + dinv*(z2[d] + sum z2[src]) --------
__global__ void pull64_kernel(const float* __restrict__ z2,
                              const int* __restrict__ row, const int* __restrict__ csr,
                              const float* __restrict__ dinv, const float* __restrict__ b2,
                              float* __restrict__ out, int n) {
    int gw = (blockIdx.x * blockDim.x + threadIdx.x) >> 5;
    int lane = threadIdx.x & 31;
    if (gw >= n) return;
    long long base = (long long)gw * OUT_C + lane * 2;
    float2 a = *reinterpret_cast<const float2*>(z2 + base);
    int beg = row[gw], end = row[gw + 1];
    int j = beg;
    for (; j + 3 < end; j += 4) {
        int s0 = csr[j], s1 = csr[j + 1], s2 = csr[j + 2], s3 = csr[j + 3];
        float2 v0 = *reinterpret_cast<const float2*>(z2 + (long long)s0 * OUT_C + lane * 2);
        float2 v1 = *reinterpret_cast<const float2*>(z2 + (long long)s1 * OUT_C + lane * 2);
        float2 v2 = *reinterpret_cast<const float2*>(z2 + (long long)s2 * OUT_C + lane * 2);
        float2 v3 = *reinterpret_cast<const float2*>(z2 + (long long)s3 * OUT_C + lane * 2);
        a.x += (v0.x + v1.x) + (v2.x + v3.x);
        a.y += (v0.y + v1.y) + (v2.y + v3.y);
    }
    for (; j < end; j++) {
        int s0 = csr[j];
        float2 v0 = *reinterpret_cast<const float2*>(z2 + (long long)s0 * OUT_C + lane * 2);
        a.x += v0.x; a.y += v0.y;
    }
    float di = dinv[gw];
    float2 bb = *reinterpret_cast<const float2*>(b2 + lane * 2);
    *reinterpret_cast<float2*>(out + base) =
        make_float2(fmaf(di, a.x, bb.x), fmaf(di, a.y, bb.y));
}

// ---------------- launch ----------------
extern "C" void kernel_launch(void* const* d_in, const int* in_sizes, int n_in,
                              void* d_out, int out_size) {
    const float* x  = (const float*)d_in[0];
    const int*   ei = (const int*)  d_in[1];
    const float* W1 = (const float*)d_in[2];
    const float* b1 = (const float*)d_in[3];
    const float* W2 = (const float*)d_in[4];
    const float* b2 = (const float*)d_in[5];
    float* out = (float*)d_out;

    const int E = in_sizes[1] / 2;
    const int* src = ei;
    const int* dst = ei + E;

    float *dinv, *h2, *agg1, *z2;
    int *degi, *row, *cur, *csr;
    unsigned long long* desc;
    __nv_bfloat16 *w1hi, *w1lo, *w2hi, *w2lo;
    cudaGetSymbolAddress((void**)&dinv, g_dinv);
    cudaGetSymbolAddress((void**)&degi, g_degi);
    cudaGetSymbolAddress((void**)&row,  g_row);
    cudaGetSymbolAddress((void**)&cur,  g_cur);
    cudaGetSymbolAddress((void**)&desc, g_desc);
    cudaGetSymbolAddress((void**)&csr,  g_csr);
    cudaGetSymbolAddress((void**)&h2,   g_h2);
    cudaGetSymbolAddress((void**)&agg1, g_agg1);
    cudaGetSymbolAddress((void**)&z2,   g_z2);
    cudaGetSymbolAddress((void**)&w1hi, g_w1hi);
    cudaGetSymbolAddress((void**)&w1lo, g_w1lo);
    cudaGetSymbolAddress((void**)&w2hi, g_w2hi);
    cudaGetSymbolAddress((void**)&w2lo, g_w2lo);

    const int LD = 72;
    const int SMEM1 = 2 * 128 * LD * 2 + 2 * 128 * LD * 2;   // 73728 B
    const int SMEM2 = 2 * 128 * LD * 2 + 2 * 64 * LD * 2;    // 55296 B
    cudaFuncSetAttribute(mma_gemm<HID_C, IN_C, false>,
                         cudaFuncAttributeMaxDynamicSharedMemorySize, SMEM1);
    cudaFuncSetAttribute(mma_gemm<OUT_C, HID_C, true>,
                         cudaFuncAttributeMaxDynamicSharedMemorySize, SMEM2);

    // 1) prep: zero degi + desc, convert W1/W2 to bf16 hi/lo [N,K]
    {
        int total = NN + NB + IN_C * HID_C + HID_C * OUT_C;
        prep_kernel<<<(total + 255) / 256, 256>>>(W1, W2, degi, desc, w1hi, w1lo, w2hi, w2lo);
    }
    // 2) degree histogram
    count_deg_kernel<<<(E + 255) / 256, 256>>>(dst, degi, E);
    // 3) single-pass scan -> row/cur + dinv
    scan_kernel<<<NB, 256>>>(degi, desc, row, cur, dinv, NN);
    // 4) CSR slot scatter
    slot_scatter_kernel<<<(E + 255) / 256, 256>>>(src, dst, cur, csr, E);

    // 5) GEMM1 (HMMA bf16x3): h2 = dinv * (x @ W1)
    mma_gemm<HID_C, IN_C, false><<<(NN + 127) / 128, 256, SMEM1>>>(
        x, w1hi, w1lo, h2, dinv, nullptr, NN);
    // 6) pull layer 1
    pull128_kernel<<<(NN * 32 + 255) / 256, 256>>>(h2, row, csr, agg1, NN);
    // 7) GEMM2 (HMMA bf16x3): z2 = dinv * (relu(b1 + dinv*agg1) @ W2)
    mma_gemm<OUT_C, HID_C, true><<<(NN + 127) / 128, 256, SMEM2>>>(
        agg1, w2hi, w2lo, z2, dinv, b1, NN);
    // 8) pull layer 2 + bias
    pull64_kernel<<<(NN * 32 + 255) / 256, 256>>>(z2, row, csr, dinv, b2, out, NN);
}

// round 9
// speedup vs baseline: 2.5416x; 1.0736x over previous
#include <cuda_runtime.h>
#include <cuda_bf16.h>
#include <cuda_fp16.h>
#include <cstdint>

#define NN     50000
#define IN_C   256
#define HID_C  128
#define OUT_C  64
#define E_MAX  800000
#define NB     ((NN + 255) / 256)   // 196 scan blocks

// ---------------- scratch ----------------
__device__ __align__(16) float g_dinv[NN];
__device__ __align__(16) int   g_degi[NN];          // zeroed at END of each call
__device__ __align__(16) int   g_row [NN + 1];
__device__ __align__(16) int   g_cur [NN];
__device__ __align__(16) unsigned long long g_desc[NB];  // zeroed at END of each call
__device__ __align__(16) int   g_csr [E_MAX];
__device__ __align__(16) __half g_h2  [NN * HID_C];  // fp16: dinv*(x@W1)
__device__ __align__(16) __half g_agg1[NN * HID_C];  // fp16: pulled layer-1 sum
__device__ __align__(16) __half g_z2  [NN * OUT_C];  // fp16: dinv*(relu@W2)
__device__ __align__(16) __nv_bfloat16 g_w1hi[HID_C * IN_C];
__device__ __align__(16) __nv_bfloat16 g_w1lo[HID_C * IN_C];
__device__ __align__(16) __nv_bfloat16 g_w2hi[OUT_C * HID_C];
__device__ __align__(16) __nv_bfloat16 g_w2lo[OUT_C * HID_C];

// ---------------- prep+count: degree histogram + weight conversion -----------
// degi must be all-zero on entry (guaranteed: zero-init at load + end-of-call reset)
__global__ void prep_count_kernel(const int* __restrict__ dst, int E,
                                  const float* __restrict__ W1, const float* __restrict__ W2,
                                  int* __restrict__ degi,
                                  __nv_bfloat16* __restrict__ w1hi, __nv_bfloat16* __restrict__ w1lo,
                                  __nv_bfloat16* __restrict__ w2hi, __nv_bfloat16* __restrict__ w2lo) {
    const int W1N = IN_C * HID_C;
    const int W2N = HID_C * OUT_C;
    int idx = blockIdx.x * blockDim.x + threadIdx.x;
    if (idx < E) {
        atomicAdd(&degi[dst[idx]], 1);
    } else if (idx < E + W1N) {
        int i = idx - E;
        int n = i / IN_C, k = i % IN_C;
        float v = W1[(long long)k * HID_C + n];
        __nv_bfloat16 hi = __float2bfloat16_rn(v);
        w1hi[i] = hi;
        w1lo[i] = __float2bfloat16_rn(v - __bfloat162float(hi));
    } else if (idx < E + W1N + W2N) {
        int i = idx - E - W1N;
        int n = i / HID_C, k = i % HID_C;
        float v = W2[(long long)k * OUT_C + n];
        __nv_bfloat16 hi = __float2bfloat16_rn(v);
        w2hi[i] = hi;
        w2lo[i] = __float2bfloat16_rn(v - __bfloat162float(hi));
    }
}

// ---------------- single-pass scan (decoupled lookback) + dinv ---------------
__global__ void scan_kernel(const int* __restrict__ deg, unsigned long long* __restrict__ desc,
                            int* __restrict__ row, int* __restrict__ cur,
                            float* __restrict__ dinv, int n) {
    __shared__ int s[256];
    __shared__ int s_carry;
    const int bid = blockIdx.x;
    const int t   = threadIdx.x;
    const int i   = bid * 256 + t;
    int v = (i < n) ? deg[i] : 0;
    s[t] = v;
    __syncthreads();
    #pragma unroll
    for (int off = 1; off < 256; off <<= 1) {
        int u = (t >= off) ? s[t - off] : 0;
        __syncthreads();
        s[t] += u;
        __syncthreads();
    }
    int total = s[255];

    if (t == 0) {
        unsigned long long d = ((unsigned long long)(bid == 0 ? 2u : 1u) << 32)
                             | (unsigned int)total;
        atomicExch(&desc[bid], d);
        if (bid == 0) s_carry = 0;
    }

    if (bid > 0 && t < 32) {
        int carry = 0;
        int j = bid - 1;
        while (true) {
            int jj = j - t;
            unsigned long long d = 0ULL;
            if (jj >= 0) d = *((volatile unsigned long long*)&desc[jj]);
            int st  = (int)(d >> 32);
            int val = (int)(d & 0xffffffffu);
            unsigned ready = __ballot_sync(0xffffffffu, (jj < 0) || st >= 1);
            if (ready != 0xffffffffu) continue;
            unsigned pmask = __ballot_sync(0xffffffffu, (jj >= 0) && st == 2);
            if (pmask) {
                int lp = __ffs(pmask) - 1;
                int contrib = (jj >= 0 && t <= lp) ? val : 0;
                #pragma unroll
                for (int o = 16; o > 0; o >>= 1)
                    contrib += __shfl_down_sync(0xffffffffu, contrib, o);
                carry += __shfl_sync(0xffffffffu, contrib, 0);
                break;
            } else {
                int contrib = (jj >= 0) ? val : 0;
                #pragma unroll
                for (int o = 16; o > 0; o >>= 1)
                    contrib += __shfl_down_sync(0xffffffffu, contrib, o);
                carry += __shfl_sync(0xffffffffu, contrib, 0);
                j -= 32;
                if (j < 0) break;
            }
        }
        if (t == 0) {
            atomicExch(&desc[bid], (2ULL << 32) | (unsigned int)(carry + total));
            s_carry = carry;
        }
    }
    __syncthreads();
    int carry = s_carry;

    if (i < n) {
        int excl = carry + s[t] - v;
        row[i] = excl;
        cur[i] = excl;
        dinv[i] = rsqrtf((float)v + 1.0f);
        if (i == n - 1) row[n] = excl + v;
    }
}

__global__ void slot_scatter_kernel(const int* __restrict__ src, const int* __restrict__ dst,
                                    int* __restrict__ cur, int* __restrict__ csr, int E) {
    int e = blockIdx.x * blockDim.x + threadIdx.x;
    if (e < E) {
        int pos = atomicAdd(&cur[dst[e]], 1);
        csr[pos] = src[e];
    }
}

// ---------------- mma.sync helper -------------------------------------------
__device__ __forceinline__ void mma16816(float c[4], const uint32_t a[4], const uint32_t b[2]) {
    asm volatile(
        "mma.sync.aligned.m16n8k16.row.col.f32.bf16.bf16.f32 "
        "{%0,%1,%2,%3}, {%4,%5,%6,%7}, {%8,%9}, {%0,%1,%2,%3};"
        : "+f"(c[0]), "+f"(c[1]), "+f"(c[2]), "+f"(c[3])
        : "r"(a[0]), "r"(a[1]), "r"(a[2]), "r"(a[3]), "r"(b[0]), "r"(b[1]));
}

// ---------------- bf16x3 HMMA GEMM ------------------------------------------
// TRANS=false: A fp32, op(A)=A             (GEMM1: x @ W1)
// TRANS=true:  A fp16, op(A)=relu(bias + dinv[r]*A)  (GEMM2)
// Output C: fp16, C = dinv[r] * acc.
template<int BN, int KTOT, bool TRANS>
__global__ void __launch_bounds__(256, 2)
mma_gemm(const void* __restrict__ Av,
         const __nv_bfloat16* __restrict__ Whi, const __nv_bfloat16* __restrict__ Wlo,
         __half* __restrict__ C,
         const float* __restrict__ dinv, const float* __restrict__ bias, int M) {
    const int BM = 128, BK = 64, LD = 72;
    const int NW = BN / 2;
    const int NT = NW / 8;
    const int A_HI = 0;
    const int A_LO = A_HI + BM * LD * 2;
    const int B_HI = A_LO + BM * LD * 2;
    const int B_LO = B_HI + BN * LD * 2;

    extern __shared__ __align__(16) char smem[];
    __nv_bfloat16* as_hi = reinterpret_cast<__nv_bfloat16*>(smem + A_HI);
    __nv_bfloat16* as_lo = reinterpret_cast<__nv_bfloat16*>(smem + A_LO);
    __nv_bfloat16* bs_hi = reinterpret_cast<__nv_bfloat16*>(smem + B_HI);
    __nv_bfloat16* bs_lo = reinterpret_cast<__nv_bfloat16*>(smem + B_LO);

    const int tid  = threadIdx.x;
    const int wid  = tid >> 5;
    const int lane = tid & 31;
    const int g    = lane >> 2;
    const int t    = lane & 3;
    const int wm   = wid & 3;
    const int wn   = wid >> 2;
    const int row0 = blockIdx.x * BM;

    float acc[2][NT > 0 ? NT : 1][4];
    #pragma unroll
    for (int mt = 0; mt < 2; mt++)
        #pragma unroll
        for (int nt = 0; nt < NT; nt++)
            #pragma unroll
            for (int q = 0; q < 4; q++) acc[mt][nt][q] = 0.0f;

    for (int kc = 0; kc < KTOT; kc += BK) {
        // ---- A tile: load (+transform) -> bf16 hi/lo ----
        #pragma unroll
        for (int it = 0; it < (BM * BK / 4) / 256; it++) {
            int idx = tid + it * 256;
            int row = idx >> 4;
            int k4  = (idx & 15) * 4;
            int gr  = row0 + row;
            float4 v = make_float4(0.f, 0.f, 0.f, 0.f);
            if (gr < M) {
                if constexpr (TRANS) {
                    const __half* Ah = reinterpret_cast<const __half*>(Av);
                    uint2 u = *reinterpret_cast<const uint2*>(Ah + (long long)gr * KTOT + kc + k4);
                    float2 f0 = __half22float2(*reinterpret_cast<__half2*>(&u.x));
                    float2 f1 = __half22float2(*reinterpret_cast<__half2*>(&u.y));
                    float di = dinv[gr];
                    float4 bb = *reinterpret_cast<const float4*>(bias + kc + k4);
                    v.x = fmaxf(fmaf(di, f0.x, bb.x), 0.f);
                    v.y = fmaxf(fmaf(di, f0.y, bb.y), 0.f);
                    v.z = fmaxf(fmaf(di, f1.x, bb.z), 0.f);
                    v.w = fmaxf(fmaf(di, f1.y, bb.w), 0.f);
                } else {
                    const float* Af = reinterpret_cast<const float*>(Av);
                    v = *reinterpret_cast<const float4*>(Af + (long long)gr * KTOT + kc + k4);
                }
            }
            __nv_bfloat162 h01 = __floats2bfloat162_rn(v.x, v.y);
            __nv_bfloat162 h23 = __floats2bfloat162_rn(v.z, v.w);
            float lx = v.x - __bfloat162float(__low2bfloat16(h01));
            float ly = v.y - __bfloat162float(__high2bfloat16(h01));
            float lz = v.z - __bfloat162float(__low2bfloat16(h23));
            float lw = v.w - __bfloat162float(__high2bfloat16(h23));
            __nv_bfloat162 l01 = __floats2bfloat162_rn(lx, ly);
            __nv_bfloat162 l23 = __floats2bfloat162_rn(lz, lw);
            int off = row * LD + k4;
            *reinterpret_cast<uint2*>(as_hi + off) =
                make_uint2(*reinterpret_cast<uint32_t*>(&h01), *reinterpret_cast<uint32_t*>(&h23));
            *reinterpret_cast<uint2*>(as_lo + off) =
                make_uint2(*reinterpret_cast<uint32_t*>(&l01), *reinterpret_cast<uint32_t*>(&l23));
        }
        // ---- B tile ----
        #pragma unroll
        for (int it = 0; it < (BN * BK / 4) / 256; it++) {
            int idx = tid + it * 256;
            int n  = idx >> 4;
            int k4 = (idx & 15) * 4;
            uint2 wh = *reinterpret_cast<const uint2*>(Whi + (long long)n * KTOT + kc + k4);
            uint2 wl = *reinterpret_cast<const uint2*>(Wlo + (long long)n * KTOT + kc + k4);
            int off = n * LD + k4;
            *reinterpret_cast<uint2*>(bs_hi + off) = wh;
            *reinterpret_cast<uint2*>(bs_lo + off) = wl;
        }
        __syncthreads();

        #pragma unroll
        for (int kk = 0; kk < BK; kk += 16) {
            uint32_t ah[2][4], al[2][4];
            #pragma unroll
            for (int mt = 0; mt < 2; mt++) {
                int ar = wm * 32 + mt * 16;
                int o00 = (ar + g) * LD + kk + 2 * t;
                int o10 = (ar + 8 + g) * LD + kk + 2 * t;
                ah[mt][0] = *reinterpret_cast<const uint32_t*>(as_hi + o00);
                ah[mt][1] = *reinterpret_cast<const uint32_t*>(as_hi + o10);
                ah[mt][2] = *reinterpret_cast<const uint32_t*>(as_hi + o00 + 8);
                ah[mt][3] = *reinterpret_cast<const uint32_t*>(as_hi + o10 + 8);
                al[mt][0] = *reinterpret_cast<const uint32_t*>(as_lo + o00);
                al[mt][1] = *reinterpret_cast<const uint32_t*>(as_lo + o10);
                al[mt][2] = *reinterpret_cast<const uint32_t*>(as_lo + o00 + 8);
                al[mt][3] = *reinterpret_cast<const uint32_t*>(as_lo + o10 + 8);
            }
            #pragma unroll
            for (int nt = 0; nt < NT; nt++) {
                int bn = wn * NW + nt * 8 + g;
                int ob = bn * LD + kk + 2 * t;
                uint32_t bh[2], bl[2];
                bh[0] = *reinterpret_cast<const uint32_t*>(bs_hi + ob);
                bh[1] = *reinterpret_cast<const uint32_t*>(bs_hi + ob + 8);
                bl[0] = *reinterpret_cast<const uint32_t*>(bs_lo + ob);
                bl[1] = *reinterpret_cast<const uint32_t*>(bs_lo + ob + 8);
                #pragma unroll
                for (int mt = 0; mt < 2; mt++) {
                    mma16816(acc[mt][nt], ah[mt], bh);
                    mma16816(acc[mt][nt], ah[mt], bl);
                    mma16816(acc[mt][nt], al[mt], bh);
                }
            }
        }
        __syncthreads();
    }

    // ---- epilogue: scale by dinv, store fp16 ----
    #pragma unroll
    for (int mt = 0; mt < 2; mt++) {
        int r0 = row0 + wm * 32 + mt * 16 + g;
        int r1 = r0 + 8;
        float s0 = (r0 < M) ? dinv[r0] : 0.0f;
        float s1 = (r1 < M) ? dinv[r1] : 0.0f;
        #pragma unroll
        for (int nt = 0; nt < NT; nt++) {
            int cc = wn * NW + nt * 8 + 2 * t;
            if (r0 < M)
                *reinterpret_cast<__half2*>(C + (long long)r0 * BN + cc) =
                    __floats2half2_rn(s0 * acc[mt][nt][0], s0 * acc[mt][nt][1]);
            if (r1 < M)
                *reinterpret_cast<__half2*>(C + (long long)r1 * BN + cc) =
                    __floats2half2_rn(s1 * acc[mt][nt][2], s1 * acc[mt][nt][3]);
        }
    }
}

// ---------------- pull layer 1 (fp16): agg1[d] = h2[d] + sum h2[src] ---------
__global__ void pull128_kernel(const __half* __restrict__ h2,
                               const int* __restrict__ row, const int* __restrict__ csr,
                               __half* __restrict__ agg, int n) {
    int gw = (blockIdx.x * blockDim.x + threadIdx.x) >> 5;
    int lane = threadIdx.x & 31;
    if (gw >= n) return;
    long long base = (long long)gw * HID_C + lane * 4;
    uint2 su = *reinterpret_cast<const uint2*>(h2 + base);
    float2 sf0 = __half22float2(*reinterpret_cast<__half2*>(&su.x));
    float2 sf1 = __half22float2(*reinterpret_cast<__half2*>(&su.y));
    float4 a = make_float4(sf0.x, sf0.y, sf1.x, sf1.y);
    int beg = row[gw], end = row[gw + 1];
    int j = beg;
    for (; j + 3 < end; j += 4) {
        int s0 = csr[j], s1 = csr[j + 1], s2 = csr[j + 2], s3 = csr[j + 3];
        uint2 u0 = *reinterpret_cast<const uint2*>(h2 + (long long)s0 * HID_C + lane * 4);
        uint2 u1 = *reinterpret_cast<const uint2*>(h2 + (long long)s1 * HID_C + lane * 4);
        uint2 u2 = *reinterpret_cast<const uint2*>(h2 + (long long)s2 * HID_C + lane * 4);
        uint2 u3 = *reinterpret_cast<const uint2*>(h2 + (long long)s3 * HID_C + lane * 4);
        float2 f;
        f = __half22float2(*reinterpret_cast<__half2*>(&u0.x)); a.x += f.x; a.y += f.y;
        f = __half22float2(*reinterpret_cast<__half2*>(&u0.y)); a.z += f.x; a.w += f.y;
        f = __half22float2(*reinterpret_cast<__half2*>(&u1.x)); a.x += f.x; a.y += f.y;
        f = __half22float2(*reinterpret_cast<__half2*>(&u1.y)); a.z += f.x; a.w += f.y;
        f = __half22float2(*reinterpret_cast<__half2*>(&u2.x)); a.x += f.x; a.y += f.y;
        f = __half22float2(*reinterpret_cast<__half2*>(&u2.y)); a.z += f.x; a.w += f.y;
        f = __half22float2(*reinterpret_cast<__half2*>(&u3.x)); a.x += f.x; a.y += f.y;
        f = __half22float2(*reinterpret_cast<__half2*>(&u3.y)); a.z += f.x; a.w += f.y;
    }
    for (; j < end; j++) {
        int s0 = csr[j];
        uint2 u0 = *reinterpret_cast<const uint2*>(h2 + (long long)s0 * HID_C + lane * 4);
        float2 f;
        f = __half22float2(*reinterpret_cast<__half2*>(&u0.x)); a.x += f.x; a.y += f.y;
        f = __half22float2(*reinterpret_cast<__half2*>(&u0.y)); a.z += f.x; a.w += f.y;
    }
    __half2 o0 = __floats2half2_rn(a.x, a.y);
    __half2 o1 = __floats2half2_rn(a.z, a.w);
    *reinterpret_cast<uint2*>(agg + base) =
        make_uint2(*reinterpret_cast<uint32_t*>(&o0), *reinterpret_cast<uint32_t*>(&o1));
}

// ---------------- pull layer 2 (fp16): out = b2 + dinv*(z2[d]+sum z2[src]) ---
// tail blocks (blockIdx >= PULL_BLOCKS) reset degi/desc for the next call
__global__ void pull64_kernel(const __half* __restrict__ z2,
                              const int* __restrict__ row, const int* __restrict__ csr,
                              const float* __restrict__ dinv, const float* __restrict__ b2,
                              float* __restrict__ out, int n,
                              int pull_blocks, int* __restrict__ degi,
                              unsigned long long* __restrict__ desc) {
    if ((int)blockIdx.x >= pull_blocks) {
        int base = ((int)blockIdx.x - pull_blocks) * 2048 + threadIdx.x * 8;
        #pragma unroll
        for (int k = 0; k < 8; k++) {
            int i = base + k;
            if (i < NN) degi[i] = 0;
            else if (i - NN < NB) desc[i - NN] = 0ULL;
        }
        return;
    }
    int gw = (blockIdx.x * blockDim.x + threadIdx.x) >> 5;
    int lane = threadIdx.x & 31;
    if (gw >= n) return;
    long long base = (long long)gw * OUT_C + lane * 2;
    float2 a = __half22float2(*reinterpret_cast<const __half2*>(z2 + base));
    int beg = row[gw], end = row[gw + 1];
    int j = beg;
    for (; j + 3 < end; j += 4) {
        int s0 = csr[j], s1 = csr[j + 1], s2 = csr[j + 2], s3 = csr[j + 3];
        float2 f0 = __half22float2(*reinterpret_cast<const __half2*>(z2 + (long long)s0 * OUT_C + lane * 2));
        float2 f1 = __half22float2(*reinterpret_cast<const __half2*>(z2 + (long long)s1 * OUT_C + lane * 2));
        float2 f2 = __half22float2(*reinterpret_cast<const __half2*>(z2 + (long long)s2 * OUT_C + lane * 2));
        float2 f3 = __half22float2(*reinterpret_cast<const __half2*>(z2 + (long long)s3 * OUT_C + lane * 2));
        a.x += (f0.x + f1.x) + (f2.x + f3.x);
        a.y += (f0.y + f1.y) + (f2.y + f3.y);
    }
    for (; j < end; j++) {
        int s0 = csr[j];
        float2 f0 = __half22float2(*reinterpret_cast<const __half2*>(z2 + (long long)s0 * OUT_C + lane * 2));
        a.x += f0.x; a.y += f0.y;
    }
    float di = dinv[gw];
    float2 bb = *reinterpret_cast<const float2*>(b2 + lane * 2);
    *reinterpret_cast<float2*>(out + base) =
        make_float2(fmaf(di, a.x, bb.x), fmaf(di, a.y, bb.y));
}

// ---------------- launch ----------------
extern "C" void kernel_launch(void* const* d_in, const int* in_sizes, int n_in,
                              void* d_out, int out_size) {
    const float* x  = (const float*)d_in[0];
    const int*   ei = (const int*)  d_in[1];
    const float* W1 = (const float*)d_in[2];
    const float* b1 = (const float*)d_in[3];
    const float* W2 = (const float*)d_in[4];
    const float* b2 = (const float*)d_in[5];
    float* out = (float*)d_out;

    const int E = in_sizes[1] / 2;
    const int* src = ei;
    const int* dst = ei + E;

    float *dinv;
    int *degi, *row, *cur, *csr;
    unsigned long long* desc;
    __half *h2, *agg1, *z2;
    __nv_bfloat16 *w1hi, *w1lo, *w2hi, *w2lo;
    cudaGetSymbolAddress((void**)&dinv, g_dinv);
    cudaGetSymbolAddress((void**)&degi, g_degi);
    cudaGetSymbolAddress((void**)&row,  g_row);
    cudaGetSymbolAddress((void**)&cur,  g_cur);
    cudaGetSymbolAddress((void**)&desc, g_desc);
    cudaGetSymbolAddress((void**)&csr,  g_csr);
    cudaGetSymbolAddress((void**)&h2,   g_h2);
    cudaGetSymbolAddress((void**)&agg1, g_agg1);
    cudaGetSymbolAddress((void**)&z2,   g_z2);
    cudaGetSymbolAddress((void**)&w1hi, g_w1hi);
    cudaGetSymbolAddress((void**)&w1lo, g_w1lo);
    cudaGetSymbolAddress((void**)&w2hi, g_w2hi);
    cudaGetSymbolAddress((void**)&w2lo, g_w2lo);

    const int LD = 72;
    const int SMEM1 = 2 * 128 * LD * 2 + 2 * 128 * LD * 2;   // 73728 B
    const int SMEM2 = 2 * 128 * LD * 2 + 2 * 64 * LD * 2;    // 55296 B
    cudaFuncSetAttribute(mma_gemm<HID_C, IN_C, false>,
                         cudaFuncAttributeMaxDynamicSharedMemorySize, SMEM1);
    cudaFuncSetAttribute(mma_gemm<OUT_C, HID_C, true>,
                         cudaFuncAttributeMaxDynamicSharedMemorySize, SMEM2);

    // 1) fused prep: degree histogram (degi pre-zeroed) + weight conversion
    {
        int total = E + IN_C * HID_C + HID_C * OUT_C;
        prep_count_kernel<<<(total + 255) / 256, 256>>>(dst, E, W1, W2, degi,
                                                        w1hi, w1lo, w2hi, w2lo);
    }
    // 2) single-pass scan -> row/cur + dinv (desc pre-zeroed)
    scan_kernel<<<NB, 256>>>(degi, desc, row, cur, dinv, NN);
    // 3) CSR slot scatter
    slot_scatter_kernel<<<(E + 255) / 256, 256>>>(src, dst, cur, csr, E);

    // 4) GEMM1 (HMMA bf16x3): h2 = fp16( dinv * (x @ W1) )
    mma_gemm<HID_C, IN_C, false><<<(NN + 127) / 128, 256, SMEM1>>>(
        x, w1hi, w1lo, h2, dinv, nullptr, NN);
    // 5) pull layer 1 (fp16 traffic)
    pull128_kernel<<<(NN * 32 + 255) / 256, 256>>>(h2, row, csr, agg1, NN);
    // 6) GEMM2 (HMMA bf16x3): z2 = fp16( dinv * (relu(b1 + dinv*agg1) @ W2) )
    mma_gemm<OUT_C, HID_C, true><<<(NN + 127) / 128, 256, SMEM2>>>(
        agg1, w2hi, w2lo, z2, dinv, b1, NN);
    // 7) pull layer 2 (fp16 traffic) + bias; tail blocks reset degi/desc
    {
        const int PULL_BLOCKS = (NN * 32 + 255) / 256;             // 6250
        const int ZERO_BLOCKS = (NN + NB + 2047) / 2048;           // 25
        pull64_kernel<<<PULL_BLOCKS + ZERO_BLOCKS, 256>>>(
            z2, row, csr, dinv, b2, out, NN, PULL_BLOCKS, degi, desc);
    }
}